// round 10
// baseline (speedup 1.0000x reference)
#include <cuda_runtime.h>
#include <cuda_fp16.h>
#include <cstdint>

// Problem constants (fixed shapes for this problem instance)
#define NODES   50000
#define EDGES   800000
#define INF     512
#define OUTF    512
#define HEADS   8
#define NBASES  4
#define FHD     64          // OUTF/HEADS
#define AGGC    256         // NBASES*FHD
#define WCOMB   32          // HEADS*NBASES
#define NCAT    800         // 256 + 32 + 512 concatenated GEMM output cols
#define RESTC   544         // WCOMB + OUTF (cols 256..799)
#define LNEPS   1e-5f

// ---------- device scratch (static allocation; no cudaMalloc allowed) ----------
__device__ float    g_wcatT[(size_t)NCAT * INF];      // transposed concat weights [800,512]
__device__ uint32_t g_bases_h[(size_t)NODES * 128];   // bases as half2 [N,128] (~25.6MB, L2-resident)
__device__ float    g_rest[(size_t)NODES * RESTC];    // comb+res outputs fp32 [N,544] (~109MB)
__device__ float    g_agg[(size_t)NODES * AGGC];      // symnorm aggregation [N,256] (~51MB)
__device__ float    g_dinv[NODES];
__device__ int      g_deg[NODES];

// ---------- zero agg + deg ----------
__global__ void zero_kernel(int nAgg4, int nDeg) {
    int i = blockIdx.x * blockDim.x + threadIdx.x;
    if (i < nAgg4) reinterpret_cast<float4*>(g_agg)[i] = make_float4(0.f, 0.f, 0.f, 0.f);
    if (i < nDeg)  g_deg[i] = 0;
}

// ---------- concat + transpose weights into g_wcatT[c][k] ----------
__global__ void concatw_kernel(const float* __restrict__ Wb,
                               const float* __restrict__ Wc,
                               const float* __restrict__ Wr) {
    int i = blockIdx.x * blockDim.x + threadIdx.x;
    if (i >= INF * NCAT) return;
    int k = i & (INF - 1);
    int c = i >> 9;
    float v;
    if (c < AGGC)              v = Wb[k * AGGC + c];
    else if (c < AGGC + WCOMB) v = Wc[k * WCOMB + (c - AGGC)];
    else                       v = Wr[k * OUTF + (c - AGGC - WCOMB)];
    g_wcatT[(size_t)c * INF + k] = v;
}

// ---------- degree count ----------
__global__ void deg_kernel(const int* __restrict__ ei, int E) {
    int i = blockIdx.x * blockDim.x + threadIdx.x;
    if (i < E) atomicAdd(&g_deg[ei[E + i]], 1);
}

__global__ void dinv_kernel(int n) {
    int i = blockIdx.x * blockDim.x + threadIdx.x;
    if (i < n) g_dinv[i] = rsqrtf((float)(g_deg[i] + 1));  // +1 self loop
}

// ---------- FP16 tensor-core GEMM (proven R8 core, split outputs) ----------
__device__ __forceinline__ void mma_f16(float* d, const uint32_t* a, const uint32_t* b) {
    asm volatile("mma.sync.aligned.m16n8k16.row.col.f32.f16.f16.f32 "
                 "{%0,%1,%2,%3},{%4,%5,%6,%7},{%8,%9},{%0,%1,%2,%3};"
                 : "+f"(d[0]), "+f"(d[1]), "+f"(d[2]), "+f"(d[3])
                 : "r"(a[0]), "r"(a[1]), "r"(a[2]), "r"(a[3]),
                   "r"(b[0]), "r"(b[1]));
}

__device__ __forceinline__ uint32_t pack_h2(float lo, float hi) {
    __half2 h = __floats2half2_rn(lo, hi);
    return *reinterpret_cast<uint32_t*>(&h);
}

#define GBM 128
#define GBN 128
#define GBK 32
#define HP  20    // row pitch in words (16 half2 used + 4 pad) -> conflict-free

__global__ __launch_bounds__(256, 2)
void f16gemm_kernel(const float* __restrict__ A, int M) {
    __shared__ uint32_t As[2][GBM][HP];
    __shared__ uint32_t Bs[2][GBN][HP];
    const int t    = threadIdx.x;
    const int wid  = t >> 5;
    const int lane = t & 31;
    const int wm   = wid & 3;
    const int wn   = wid >> 2;
    const int lr   = lane >> 2;
    const int lc   = lane & 3;
    const int m0   = blockIdx.y * GBM;
    const int n0   = blockIdx.x * GBN;

    float acc[2][8][4];
#pragma unroll
    for (int mt = 0; mt < 2; mt++)
#pragma unroll
        for (int nt = 0; nt < 8; nt++)
#pragma unroll
            for (int r = 0; r < 4; r++) acc[mt][nt][r] = 0.f;

    float4 pa[2][2], pb[2][2];

    auto loadA = [&](int kt) {
#pragma unroll
        for (int i = 0; i < 2; i++) {
            int f   = t + i * 256;
            int row = f >> 2;
            int q4  = (f & 3) * 4;
            int gr  = m0 + row;
            const float* src = A + (size_t)gr * INF + kt + q4 * 2;
            if (gr < M) {
                pa[i][0] = *reinterpret_cast<const float4*>(src);
                pa[i][1] = *reinterpret_cast<const float4*>(src + 4);
            } else {
                pa[i][0] = pa[i][1] = make_float4(0.f, 0.f, 0.f, 0.f);
            }
        }
    };
    auto loadB = [&](int kt) {
#pragma unroll
        for (int i = 0; i < 2; i++) {
            int f   = t + i * 256;
            int row = f >> 2;
            int q4  = (f & 3) * 4;
            int gn  = n0 + row;
            const float* src = g_wcatT + (size_t)gn * INF + kt + q4 * 2;
            if (gn < NCAT) {
                pb[i][0] = *reinterpret_cast<const float4*>(src);
                pb[i][1] = *reinterpret_cast<const float4*>(src + 4);
            } else {
                pb[i][0] = pb[i][1] = make_float4(0.f, 0.f, 0.f, 0.f);
            }
        }
    };

    loadA(0);
    loadB(0);
    int buf = 0;

    for (int kt = 0; kt < INF; kt += GBK) {
#pragma unroll
        for (int i = 0; i < 2; i++) {
            int f   = t + i * 256;
            int row = f >> 2;
            int q4  = (f & 3) * 4;
            uint4 ua = make_uint4(pack_h2(pa[i][0].x, pa[i][0].y),
                                  pack_h2(pa[i][0].z, pa[i][0].w),
                                  pack_h2(pa[i][1].x, pa[i][1].y),
                                  pack_h2(pa[i][1].z, pa[i][1].w));
            *reinterpret_cast<uint4*>(&As[buf][row][q4]) = ua;
            uint4 ub = make_uint4(pack_h2(pb[i][0].x, pb[i][0].y),
                                  pack_h2(pb[i][0].z, pb[i][0].w),
                                  pack_h2(pb[i][1].x, pb[i][1].y),
                                  pack_h2(pb[i][1].z, pb[i][1].w));
            *reinterpret_cast<uint4*>(&Bs[buf][row][q4]) = ub;
        }
        __syncthreads();

        if (kt + GBK < INF) {
            loadA(kt + GBK);
            loadB(kt + GBK);
        }

#pragma unroll
        for (int s = 0; s < 2; s++) {
            const int ko = s * 8;
            uint32_t af[2][4];
#pragma unroll
            for (int mt = 0; mt < 2; mt++) {
                int r0 = wm * 32 + mt * 16 + lr;
                af[mt][0] = As[buf][r0][ko + lc];
                af[mt][1] = As[buf][r0 + 8][ko + lc];
                af[mt][2] = As[buf][r0][ko + lc + 4];
                af[mt][3] = As[buf][r0 + 8][ko + lc + 4];
            }
#pragma unroll
            for (int nt = 0; nt < 8; nt++) {
                int col = wn * 64 + nt * 8 + lr;
                uint32_t bf[2];
                bf[0] = Bs[buf][col][ko + lc];
                bf[1] = Bs[buf][col][ko + lc + 4];
#pragma unroll
                for (int mt = 0; mt < 2; mt++)
                    mma_f16(acc[mt][nt], af[mt], bf);
            }
        }
        buf ^= 1;
    }

    // store: n-blocks 0..1 are pure bases (fp16); blocks 2..6 are rest (fp32)
    const bool isBases = (n0 < AGGC);
#pragma unroll
    for (int mt = 0; mt < 2; mt++) {
#pragma unroll
        for (int nt = 0; nt < 8; nt++) {
            int row = m0 + wm * 32 + mt * 16 + lr;
            int col = n0 + wn * 64 + nt * 8 + 2 * lc;
            if (isBases) {
                if (row < M)
                    g_bases_h[(size_t)row * 128 + (col >> 1)] =
                        pack_h2(acc[mt][nt][0], acc[mt][nt][1]);
                if (row + 8 < M)
                    g_bases_h[(size_t)(row + 8) * 128 + (col >> 1)] =
                        pack_h2(acc[mt][nt][2], acc[mt][nt][3]);
            } else if (col < NCAT) {
                int rc = col - AGGC;
                if (row < M) {
                    float2 v = make_float2(acc[mt][nt][0], acc[mt][nt][1]);
                    *reinterpret_cast<float2*>(g_rest + (size_t)row * RESTC + rc) = v;
                }
                if (row + 8 < M) {
                    float2 v = make_float2(acc[mt][nt][2], acc[mt][nt][3]);
                    *reinterpret_cast<float2*>(g_rest + (size_t)(row + 8) * RESTC + rc) = v;
                }
            }
        }
    }
}

// ---------- edge scatter: agg[dst] += bases_h[src] * nrm ----------
// one warp per edge; per lane: 1 LDG.128 (4 half2) + 2 red.v4
__device__ __forceinline__ void red_add_v4(float* addr, float a, float b, float c, float d) {
    asm volatile("red.global.add.v4.f32 [%0], {%1, %2, %3, %4};"
                 :: "l"(addr), "f"(a), "f"(b), "f"(c), "f"(d) : "memory");
}

__global__ void scatter_kernel(const int* __restrict__ ei, int E) {
    int w = (blockIdx.x * blockDim.x + threadIdx.x) >> 5;
    if (w >= E) return;
    int lane = threadIdx.x & 31;
    int src = __ldg(ei + w);
    int dst = __ldg(ei + E + w);
    float nrm = __ldg(g_dinv + src) * __ldg(g_dinv + dst);
    const uint4* brow = reinterpret_cast<const uint4*>(g_bases_h + (size_t)src * 128);
    float* arow = g_agg + (size_t)dst * AGGC + lane * 8;

    uint4 h = __ldg(brow + lane);
    float2 f0 = __half22float2(*reinterpret_cast<__half2*>(&h.x));
    float2 f1 = __half22float2(*reinterpret_cast<__half2*>(&h.y));
    float2 f2 = __half22float2(*reinterpret_cast<__half2*>(&h.z));
    float2 f3 = __half22float2(*reinterpret_cast<__half2*>(&h.w));
    red_add_v4(arow,     f0.x * nrm, f0.y * nrm, f1.x * nrm, f1.y * nrm);
    red_add_v4(arow + 4, f2.x * nrm, f2.y * nrm, f3.x * nrm, f3.y * nrm);
}

// ---------- combine: einsum + biases + residual + LayerNorm + ReLU ----------
__global__ __launch_bounds__(128)
void combine_kernel(const float* __restrict__ b_comb,
                    const float* __restrict__ conv_bias,
                    const float* __restrict__ b_res,
                    const float* __restrict__ gamma,
                    const float* __restrict__ beta,
                    float* __restrict__ out) {
    int v = blockIdx.x;
    int tid = threadIdx.x;
    __shared__ float sagg[AGGC];
    __shared__ float sw[WCOMB];
    __shared__ float red[8];

    float d = g_dinv[v];
    float d2 = d * d;
    const float* rc = g_rest + (size_t)v * RESTC;
    const float* ag = g_agg + (size_t)v * AGGC;

    // agg row + self-loop term (bases from fp16 copy)
    {
        uint32_t h = g_bases_h[(size_t)v * 128 + tid];
        float2 bf = __half22float2(*reinterpret_cast<__half2*>(&h));
        float2 av = *reinterpret_cast<const float2*>(ag + 2 * tid);
        sagg[2 * tid]     = av.x + bf.x * d2;
        sagg[2 * tid + 1] = av.y + bf.y * d2;
    }
    if (tid < WCOMB) sw[tid] = rc[tid] + b_comb[tid];
    __syncthreads();

    float val[4];
    float s = 0.f, sq = 0.f;
#pragma unroll
    for (int j = 0; j < 4; j++) {
        int c = tid + j * 128;
        int h = c >> 6, f = c & 63;
        const float* wv = &sw[h * 4];
        float a = wv[0] * sagg[f]
                + wv[1] * sagg[64 + f]
                + wv[2] * sagg[128 + f]
                + wv[3] * sagg[192 + f];
        a += conv_bias[c] + rc[WCOMB + c] + b_res[c];
        val[j] = a;
        s += a;
        sq += a * a;
    }
#pragma unroll
    for (int o = 16; o > 0; o >>= 1) {
        s  += __shfl_xor_sync(0xffffffffu, s, o);
        sq += __shfl_xor_sync(0xffffffffu, sq, o);
    }
    if ((tid & 31) == 0) { red[tid >> 5] = s; red[4 + (tid >> 5)] = sq; }
    __syncthreads();
    s  = red[0] + red[1] + red[2] + red[3];
    sq = red[4] + red[5] + red[6] + red[7];
    float mean = s * (1.f / OUTF);
    float var  = sq * (1.f / OUTF) - mean * mean;
    float rstd = rsqrtf(var + LNEPS);
#pragma unroll
    for (int j = 0; j < 4; j++) {
        int c = tid + j * 128;
        float o = (val[j] - mean) * rstd * gamma[c] + beta[c];
        out[(size_t)v * OUTF + c] = fmaxf(o, 0.f);
    }
}

extern "C" void kernel_launch(void* const* d_in, const int* in_sizes, int n_in,
                              void* d_out, int out_size) {
    const float* x     = (const float*)d_in[0];
    const int*   ei    = (const int*)  d_in[1];
    const float* Wb    = (const float*)d_in[2];
    const float* Wc    = (const float*)d_in[3];
    const float* bcomb = (const float*)d_in[4];
    const float* cbias = (const float*)d_in[5];
    const float* Wr    = (const float*)d_in[6];
    const float* bres  = (const float*)d_in[7];
    const float* gamma = (const float*)d_in[8];
    const float* beta  = (const float*)d_in[9];
    float* out = (float*)d_out;

    const int N = in_sizes[0] / INF;
    const int E = in_sizes[1] / 2;

    // 1. zero agg + deg
    {
        int nAgg4 = (N * AGGC) / 4;
        zero_kernel<<<(nAgg4 + 255) / 256, 256>>>(nAgg4, N);
    }
    // 2. concat + transpose weights
    concatw_kernel<<<(INF * NCAT + 255) / 256, 256>>>(Wb, Wc, Wr);
    // 3. degrees
    deg_kernel<<<(E + 255) / 256, 256>>>(ei, E);
    dinv_kernel<<<(N + 255) / 256, 256>>>(N);
    // 4. fused GEMM (FP16 tensor cores, fp32 accum, split fp16/fp32 outputs)
    {
        dim3 grid((NCAT + GBN - 1) / GBN, (N + GBM - 1) / GBM);
        f16gemm_kernel<<<grid, 256>>>(x, N);
    }
    // 5. edge scatter (fp16 bases reads, v4 reduction atomics)
    {
        long long threads = (long long)E * 32;
        int blocks = (int)((threads + 255) / 256);
        scatter_kernel<<<blocks, 256>>>(ei, E);
    }
    // 6. combine + LayerNorm + ReLU
    combine_kernel<<<N, 128>>>(bcomb, cbias, bres, gamma, beta, out);
}

// round 11
// speedup vs baseline: 1.1392x; 1.1392x over previous
#include <cuda_runtime.h>
#include <cuda_fp16.h>
#include <cstdint>

// Problem constants (fixed shapes for this problem instance)
#define NODES   50000
#define EDGES   800000
#define INF     512
#define OUTF    512
#define HEADS   8
#define NBASES  4
#define FHD     64          // OUTF/HEADS
#define AGGC    256         // NBASES*FHD
#define WCOMB   32          // HEADS*NBASES
#define NCAT    800         // 256 + 32 + 512 concatenated GEMM output cols
#define LNEPS   1e-5f

// ---------- device scratch (static allocation; no cudaMalloc allowed) ----------
__device__ float    g_wcatT[(size_t)NCAT * INF];      // transposed concat weights [800,512]
__device__ float    g_cat[(size_t)NODES * NCAT];      // x @ Wcat  [N,800]  (~160MB)
__device__ uint32_t g_bases_h[(size_t)NODES * 128];   // bases as half2 [N,128] (~25.6MB, L2-resident)
__device__ float    g_agg[(size_t)NODES * AGGC];      // symnorm aggregation [N,256] (~51MB)
__device__ float    g_dinv[NODES];
__device__ int      g_deg[NODES];

// ---------- zero agg + deg ----------
__global__ void zero_kernel(int nAgg4, int nDeg) {
    int i = blockIdx.x * blockDim.x + threadIdx.x;
    if (i < nAgg4) reinterpret_cast<float4*>(g_agg)[i] = make_float4(0.f, 0.f, 0.f, 0.f);
    if (i < nDeg)  g_deg[i] = 0;
}

// ---------- concat + transpose weights into g_wcatT[c][k] ----------
__global__ void concatw_kernel(const float* __restrict__ Wb,
                               const float* __restrict__ Wc,
                               const float* __restrict__ Wr) {
    int i = blockIdx.x * blockDim.x + threadIdx.x;
    if (i >= INF * NCAT) return;
    int k = i & (INF - 1);
    int c = i >> 9;
    float v;
    if (c < AGGC)              v = Wb[k * AGGC + c];
    else if (c < AGGC + WCOMB) v = Wc[k * WCOMB + (c - AGGC)];
    else                       v = Wr[k * OUTF + (c - AGGC - WCOMB)];
    g_wcatT[(size_t)c * INF + k] = v;
}

// ---------- degree count ----------
__global__ void deg_kernel(const int* __restrict__ ei, int E) {
    int i = blockIdx.x * blockDim.x + threadIdx.x;
    if (i < E) atomicAdd(&g_deg[ei[E + i]], 1);
}

__global__ void dinv_kernel(int n) {
    int i = blockIdx.x * blockDim.x + threadIdx.x;
    if (i < n) g_dinv[i] = rsqrtf((float)(g_deg[i] + 1));  // +1 self loop
}

// ---------- FP16 tensor-core GEMM (R8 core, + fp16 bases side-write) ----------
__device__ __forceinline__ void mma_f16(float* d, const uint32_t* a, const uint32_t* b) {
    asm volatile("mma.sync.aligned.m16n8k16.row.col.f32.f16.f16.f32 "
                 "{%0,%1,%2,%3},{%4,%5,%6,%7},{%8,%9},{%0,%1,%2,%3};"
                 : "+f"(d[0]), "+f"(d[1]), "+f"(d[2]), "+f"(d[3])
                 : "r"(a[0]), "r"(a[1]), "r"(a[2]), "r"(a[3]),
                   "r"(b[0]), "r"(b[1]));
}

__device__ __forceinline__ uint32_t pack_h2(float lo, float hi) {
    __half2 h = __floats2half2_rn(lo, hi);
    return *reinterpret_cast<uint32_t*>(&h);
}

#define GBM 128
#define GBN 128
#define GBK 32
#define HP  20    // row pitch in words (16 half2 used + 4 pad) -> conflict-free

__global__ __launch_bounds__(256, 2)
void f16gemm_kernel(const float* __restrict__ A, int M) {
    __shared__ uint32_t As[2][GBM][HP];
    __shared__ uint32_t Bs[2][GBN][HP];
    const int t    = threadIdx.x;
    const int wid  = t >> 5;
    const int lane = t & 31;
    const int wm   = wid & 3;
    const int wn   = wid >> 2;
    const int lr   = lane >> 2;
    const int lc   = lane & 3;
    const int m0   = blockIdx.y * GBM;
    const int n0   = blockIdx.x * GBN;

    float acc[2][8][4];
#pragma unroll
    for (int mt = 0; mt < 2; mt++)
#pragma unroll
        for (int nt = 0; nt < 8; nt++)
#pragma unroll
            for (int r = 0; r < 4; r++) acc[mt][nt][r] = 0.f;

    float4 pa[2][2], pb[2][2];

    auto loadA = [&](int kt) {
#pragma unroll
        for (int i = 0; i < 2; i++) {
            int f   = t + i * 256;
            int row = f >> 2;
            int q4  = (f & 3) * 4;
            int gr  = m0 + row;
            const float* src = A + (size_t)gr * INF + kt + q4 * 2;
            if (gr < M) {
                pa[i][0] = *reinterpret_cast<const float4*>(src);
                pa[i][1] = *reinterpret_cast<const float4*>(src + 4);
            } else {
                pa[i][0] = pa[i][1] = make_float4(0.f, 0.f, 0.f, 0.f);
            }
        }
    };
    auto loadB = [&](int kt) {
#pragma unroll
        for (int i = 0; i < 2; i++) {
            int f   = t + i * 256;
            int row = f >> 2;
            int q4  = (f & 3) * 4;
            int gn  = n0 + row;
            const float* src = g_wcatT + (size_t)gn * INF + kt + q4 * 2;
            if (gn < NCAT) {
                pb[i][0] = *reinterpret_cast<const float4*>(src);
                pb[i][1] = *reinterpret_cast<const float4*>(src + 4);
            } else {
                pb[i][0] = pb[i][1] = make_float4(0.f, 0.f, 0.f, 0.f);
            }
        }
    };

    loadA(0);
    loadB(0);
    int buf = 0;

    for (int kt = 0; kt < INF; kt += GBK) {
#pragma unroll
        for (int i = 0; i < 2; i++) {
            int f   = t + i * 256;
            int row = f >> 2;
            int q4  = (f & 3) * 4;
            uint4 ua = make_uint4(pack_h2(pa[i][0].x, pa[i][0].y),
                                  pack_h2(pa[i][0].z, pa[i][0].w),
                                  pack_h2(pa[i][1].x, pa[i][1].y),
                                  pack_h2(pa[i][1].z, pa[i][1].w));
            *reinterpret_cast<uint4*>(&As[buf][row][q4]) = ua;
            uint4 ub = make_uint4(pack_h2(pb[i][0].x, pb[i][0].y),
                                  pack_h2(pb[i][0].z, pb[i][0].w),
                                  pack_h2(pb[i][1].x, pb[i][1].y),
                                  pack_h2(pb[i][1].z, pb[i][1].w));
            *reinterpret_cast<uint4*>(&Bs[buf][row][q4]) = ub;
        }
        __syncthreads();

        if (kt + GBK < INF) {
            loadA(kt + GBK);
            loadB(kt + GBK);
        }

#pragma unroll
        for (int s = 0; s < 2; s++) {
            const int ko = s * 8;
            uint32_t af[2][4];
#pragma unroll
            for (int mt = 0; mt < 2; mt++) {
                int r0 = wm * 32 + mt * 16 + lr;
                af[mt][0] = As[buf][r0][ko + lc];
                af[mt][1] = As[buf][r0 + 8][ko + lc];
                af[mt][2] = As[buf][r0][ko + lc + 4];
                af[mt][3] = As[buf][r0 + 8][ko + lc + 4];
            }
#pragma unroll
            for (int nt = 0; nt < 8; nt++) {
                int col = wn * 64 + nt * 8 + lr;
                uint32_t bf[2];
                bf[0] = Bs[buf][col][ko + lc];
                bf[1] = Bs[buf][col][ko + lc + 4];
#pragma unroll
                for (int mt = 0; mt < 2; mt++)
                    mma_f16(acc[mt][nt], af[mt], bf);
            }
        }
        buf ^= 1;
    }

    // store fp32 to g_cat (unchanged); bases cols additionally as half2
#pragma unroll
    for (int mt = 0; mt < 2; mt++) {
#pragma unroll
        for (int nt = 0; nt < 8; nt++) {
            int row = m0 + wm * 32 + mt * 16 + lr;
            int col = n0 + wn * 64 + nt * 8 + 2 * lc;
            if (col < NCAT) {
                if (row < M) {
                    float2 v = make_float2(acc[mt][nt][0], acc[mt][nt][1]);
                    *reinterpret_cast<float2*>(g_cat + (size_t)row * NCAT + col) = v;
                    if (col < AGGC)
                        g_bases_h[(size_t)row * 128 + (col >> 1)] = pack_h2(v.x, v.y);
                }
                if (row + 8 < M) {
                    float2 v = make_float2(acc[mt][nt][2], acc[mt][nt][3]);
                    *reinterpret_cast<float2*>(g_cat + (size_t)(row + 8) * NCAT + col) = v;
                    if (col < AGGC)
                        g_bases_h[(size_t)(row + 8) * 128 + (col >> 1)] = pack_h2(v.x, v.y);
                }
            }
        }
    }
}

// ---------- edge scatter: agg[dst] += bases_h[src] * nrm ----------
// one warp per edge; 2 independent 8B loads per lane (same MLP + RED address
// pattern as the 469us baseline; only read bytes halve).
__device__ __forceinline__ void red_add_v4(float* addr, float a, float b, float c, float d) {
    asm volatile("red.global.add.v4.f32 [%0], {%1, %2, %3, %4};"
                 :: "l"(addr), "f"(a), "f"(b), "f"(c), "f"(d) : "memory");
}

__global__ void scatter_kernel(const int* __restrict__ ei, int E) {
    int w = (blockIdx.x * blockDim.x + threadIdx.x) >> 5;
    if (w >= E) return;
    int lane = threadIdx.x & 31;
    int src = __ldg(ei + w);
    int dst = __ldg(ei + E + w);
    float nrm = __ldg(g_dinv + src) * __ldg(g_dinv + dst);
    const uint2* brow = reinterpret_cast<const uint2*>(g_bases_h + (size_t)src * 128);
    float* arow = g_agg + (size_t)dst * AGGC;
#pragma unroll
    for (int i = 0; i < 2; i++) {
        int q = lane + i * 32;                       // uint2 index 0..63
        uint2 h = __ldg(brow + q);
        float2 f0 = __half22float2(*reinterpret_cast<__half2*>(&h.x));
        float2 f1 = __half22float2(*reinterpret_cast<__half2*>(&h.y));
        red_add_v4(arow + q * 4, f0.x * nrm, f0.y * nrm, f1.x * nrm, f1.y * nrm);
    }
}

// ---------- combine: einsum + biases + residual + LayerNorm + ReLU ----------
__global__ __launch_bounds__(128)
void combine_kernel(const float* __restrict__ b_comb,
                    const float* __restrict__ conv_bias,
                    const float* __restrict__ b_res,
                    const float* __restrict__ gamma,
                    const float* __restrict__ beta,
                    float* __restrict__ out) {
    int v = blockIdx.x;
    int tid = threadIdx.x;
    __shared__ float sagg[AGGC];
    __shared__ float sw[WCOMB];
    __shared__ float red[8];

    float d = g_dinv[v];
    float d2 = d * d;
    const float* oc = g_cat + (size_t)v * NCAT;
    const float* ag = g_agg + (size_t)v * AGGC;

    // agg row + self-loop term (fp32 bases from g_cat, as in 469us baseline)
#pragma unroll
    for (int j = 0; j < 2; j++) {
        int i = tid + j * 128;
        sagg[i] = ag[i] + oc[i] * d2;
    }
    if (tid < WCOMB) sw[tid] = oc[AGGC + tid] + b_comb[tid];
    __syncthreads();

    float val[4];
    float s = 0.f, sq = 0.f;
#pragma unroll
    for (int j = 0; j < 4; j++) {
        int c = tid + j * 128;
        int h = c >> 6, f = c & 63;
        const float* wv = &sw[h * 4];
        float a = wv[0] * sagg[f]
                + wv[1] * sagg[64 + f]
                + wv[2] * sagg[128 + f]
                + wv[3] * sagg[192 + f];
        a += conv_bias[c] + oc[AGGC + WCOMB + c] + b_res[c];
        val[j] = a;
        s += a;
        sq += a * a;
    }
#pragma unroll
    for (int o = 16; o > 0; o >>= 1) {
        s  += __shfl_xor_sync(0xffffffffu, s, o);
        sq += __shfl_xor_sync(0xffffffffu, sq, o);
    }
    if ((tid & 31) == 0) { red[tid >> 5] = s; red[4 + (tid >> 5)] = sq; }
    __syncthreads();
    s  = red[0] + red[1] + red[2] + red[3];
    sq = red[4] + red[5] + red[6] + red[7];
    float mean = s * (1.f / OUTF);
    float var  = sq * (1.f / OUTF) - mean * mean;
    float rstd = rsqrtf(var + LNEPS);
#pragma unroll
    for (int j = 0; j < 4; j++) {
        int c = tid + j * 128;
        float o = (val[j] - mean) * rstd * gamma[c] + beta[c];
        out[(size_t)v * OUTF + c] = fmaxf(o, 0.f);
    }
}

extern "C" void kernel_launch(void* const* d_in, const int* in_sizes, int n_in,
                              void* d_out, int out_size) {
    const float* x     = (const float*)d_in[0];
    const int*   ei    = (const int*)  d_in[1];
    const float* Wb    = (const float*)d_in[2];
    const float* Wc    = (const float*)d_in[3];
    const float* bcomb = (const float*)d_in[4];
    const float* cbias = (const float*)d_in[5];
    const float* Wr    = (const float*)d_in[6];
    const float* bres  = (const float*)d_in[7];
    const float* gamma = (const float*)d_in[8];
    const float* beta  = (const float*)d_in[9];
    float* out = (float*)d_out;

    const int N = in_sizes[0] / INF;
    const int E = in_sizes[1] / 2;

    // 1. zero agg + deg
    {
        int nAgg4 = (N * AGGC) / 4;
        zero_kernel<<<(nAgg4 + 255) / 256, 256>>>(nAgg4, N);
    }
    // 2. concat + transpose weights
    concatw_kernel<<<(INF * NCAT + 255) / 256, 256>>>(Wb, Wc, Wr);
    // 3. degrees
    deg_kernel<<<(E + 255) / 256, 256>>>(ei, E);
    dinv_kernel<<<(N + 255) / 256, 256>>>(N);
    // 4. fused GEMM (FP16 tensor cores, double-buffered, + fp16 bases copy)
    {
        dim3 grid((NCAT + GBN - 1) / GBN, (N + GBM - 1) / GBM);
        f16gemm_kernel<<<grid, 256>>>(x, N);
    }
    // 5. edge scatter (fp16 bases reads, v4 reduction atomics)
    {
        long long threads = (long long)E * 32;
        int blocks = (int)((threads + 255) / 256);
        scatter_kernel<<<blocks, 256>>>(ei, E);
    }
    // 6. combine + LayerNorm + ReLU
    combine_kernel<<<N, 128>>>(bcomb, cbias, bres, gamma, beta, out);
}

// round 12
// speedup vs baseline: 1.2015x; 1.0547x over previous
#include <cuda_runtime.h>
#include <cuda_fp16.h>
#include <cstdint>

// Problem constants (fixed shapes for this problem instance)
#define NODES   50000
#define EDGES   800000
#define INF     512
#define OUTF    512
#define HEADS   8
#define NBASES  4
#define FHD     64          // OUTF/HEADS
#define AGGC    256         // NBASES*FHD
#define WCOMB   32          // HEADS*NBASES
#define NCAT    800         // 256 + 32 + 512 concatenated GEMM output cols
#define LNEPS   1e-5f

// ---------- device scratch (static allocation; no cudaMalloc allowed) ----------
__device__ float    g_wcatT[(size_t)NCAT * INF];      // transposed concat weights [800,512]
__device__ float    g_cat[(size_t)NODES * NCAT];      // x @ Wcat  [N,800]  (~160MB)
__device__ uint32_t g_bases_h[(size_t)NODES * 128];   // bases as half2 [N,128] (~25.6MB)
__device__ float    g_agg[(size_t)NODES * AGGC];      // symnorm aggregation [N,256] (~51MB)
__device__ float    g_dinv[NODES];
__device__ int      g_deg[NODES];

// ---------- zero agg + deg ----------
__global__ void zero_kernel(int nAgg4, int nDeg) {
    int i = blockIdx.x * blockDim.x + threadIdx.x;
    if (i < nAgg4) reinterpret_cast<float4*>(g_agg)[i] = make_float4(0.f, 0.f, 0.f, 0.f);
    if (i < nDeg)  g_deg[i] = 0;
}

// ---------- concat + transpose weights into g_wcatT[c][k] ----------
__global__ void concatw_kernel(const float* __restrict__ Wb,
                               const float* __restrict__ Wc,
                               const float* __restrict__ Wr) {
    int i = blockIdx.x * blockDim.x + threadIdx.x;
    if (i >= INF * NCAT) return;
    int k = i & (INF - 1);
    int c = i >> 9;
    float v;
    if (c < AGGC)              v = Wb[k * AGGC + c];
    else if (c < AGGC + WCOMB) v = Wc[k * WCOMB + (c - AGGC)];
    else                       v = Wr[k * OUTF + (c - AGGC - WCOMB)];
    g_wcatT[(size_t)c * INF + k] = v;
}

// ---------- degree count ----------
__global__ void deg_kernel(const int* __restrict__ ei, int E) {
    int i = blockIdx.x * blockDim.x + threadIdx.x;
    if (i < E) atomicAdd(&g_deg[ei[E + i]], 1);
}

__global__ void dinv_kernel(int n) {
    int i = blockIdx.x * blockDim.x + threadIdx.x;
    if (i < n) g_dinv[i] = rsqrtf((float)(g_deg[i] + 1));  // +1 self loop
}

// ---------- FP16 tensor-core GEMM (R8 core, ldmatrix fragment loads) ----------
__device__ __forceinline__ void mma_f16(float* d, const uint32_t* a, const uint32_t* b) {
    asm volatile("mma.sync.aligned.m16n8k16.row.col.f32.f16.f16.f32 "
                 "{%0,%1,%2,%3},{%4,%5,%6,%7},{%8,%9},{%0,%1,%2,%3};"
                 : "+f"(d[0]), "+f"(d[1]), "+f"(d[2]), "+f"(d[3])
                 : "r"(a[0]), "r"(a[1]), "r"(a[2]), "r"(a[3]),
                   "r"(b[0]), "r"(b[1]));
}

__device__ __forceinline__ void ldsm_x4(uint32_t& r0, uint32_t& r1,
                                        uint32_t& r2, uint32_t& r3, uint32_t addr) {
    asm volatile("ldmatrix.sync.aligned.m8n8.x4.shared.b16 {%0,%1,%2,%3}, [%4];"
                 : "=r"(r0), "=r"(r1), "=r"(r2), "=r"(r3) : "r"(addr));
}

__device__ __forceinline__ uint32_t pack_h2(float lo, float hi) {
    __half2 h = __floats2half2_rn(lo, hi);
    return *reinterpret_cast<uint32_t*>(&h);
}

__device__ __forceinline__ uint32_t smem_u32(const void* p) {
    uint32_t a;
    asm("{ .reg .u64 t; cvta.to.shared.u64 t, %1; cvt.u32.u64 %0, t; }" : "=r"(a) : "l"(p));
    return a;
}

#define GBM 128
#define GBN 128
#define GBK 32
#define HP  20    // row pitch in words (16 half2 used + 4 pad) -> conflict-free

__global__ __launch_bounds__(256, 2)
void f16gemm_kernel(const float* __restrict__ A, int M) {
    __shared__ uint32_t As[2][GBM][HP];
    __shared__ uint32_t Bs[2][GBN][HP];
    const int t    = threadIdx.x;
    const int wid  = t >> 5;
    const int lane = t & 31;
    const int wm   = wid & 3;
    const int wn   = wid >> 2;
    const int lr   = lane >> 2;
    const int lc   = lane & 3;
    const int m0   = blockIdx.y * GBM;
    const int n0   = blockIdx.x * GBN;

    // ldmatrix per-lane addressing: matrix id = lane>>3
    // row offset within 16-row tile = (lane&7) + ((lane>>3)&1)*8
    // word-col offset = (lane>>4)*4  (k halves 0-7 vs 8-15 of the step)
    const int lrow = (lane & 7) + ((lane >> 3) & 1) * 8;
    const int lcol = (lane >> 4) * 4;
    const uint32_t sbA = smem_u32(&As[0][0][0]);
    const uint32_t sbB = smem_u32(&Bs[0][0][0]);
    uint32_t aAddr[2], bAddr[4];
#pragma unroll
    for (int mt = 0; mt < 2; mt++)
        aAddr[mt] = sbA + (uint32_t)(((wm * 32 + mt * 16 + lrow) * HP + lcol) * 4);
#pragma unroll
    for (int ng = 0; ng < 4; ng++)
        bAddr[ng] = sbB + (uint32_t)(((wn * 64 + ng * 16 + lrow) * HP + lcol) * 4);
    const uint32_t bufA = (uint32_t)(GBM * HP * 4);
    const uint32_t bufB = (uint32_t)(GBN * HP * 4);

    float acc[2][8][4];
#pragma unroll
    for (int mt = 0; mt < 2; mt++)
#pragma unroll
        for (int nt = 0; nt < 8; nt++)
#pragma unroll
            for (int r = 0; r < 4; r++) acc[mt][nt][r] = 0.f;

    float4 pa[2][2], pb[2][2];

    auto loadA = [&](int kt) {
#pragma unroll
        for (int i = 0; i < 2; i++) {
            int f   = t + i * 256;
            int row = f >> 2;
            int q4  = (f & 3) * 4;
            int gr  = m0 + row;
            const float* src = A + (size_t)gr * INF + kt + q4 * 2;
            if (gr < M) {
                pa[i][0] = *reinterpret_cast<const float4*>(src);
                pa[i][1] = *reinterpret_cast<const float4*>(src + 4);
            } else {
                pa[i][0] = pa[i][1] = make_float4(0.f, 0.f, 0.f, 0.f);
            }
        }
    };
    auto loadB = [&](int kt) {
#pragma unroll
        for (int i = 0; i < 2; i++) {
            int f   = t + i * 256;
            int row = f >> 2;
            int q4  = (f & 3) * 4;
            int gn  = n0 + row;
            const float* src = g_wcatT + (size_t)gn * INF + kt + q4 * 2;
            if (gn < NCAT) {
                pb[i][0] = *reinterpret_cast<const float4*>(src);
                pb[i][1] = *reinterpret_cast<const float4*>(src + 4);
            } else {
                pb[i][0] = pb[i][1] = make_float4(0.f, 0.f, 0.f, 0.f);
            }
        }
    };

    loadA(0);
    loadB(0);
    int buf = 0;

    for (int kt = 0; kt < INF; kt += GBK) {
#pragma unroll
        for (int i = 0; i < 2; i++) {
            int f   = t + i * 256;
            int row = f >> 2;
            int q4  = (f & 3) * 4;
            uint4 ua = make_uint4(pack_h2(pa[i][0].x, pa[i][0].y),
                                  pack_h2(pa[i][0].z, pa[i][0].w),
                                  pack_h2(pa[i][1].x, pa[i][1].y),
                                  pack_h2(pa[i][1].z, pa[i][1].w));
            *reinterpret_cast<uint4*>(&As[buf][row][q4]) = ua;
            uint4 ub = make_uint4(pack_h2(pb[i][0].x, pb[i][0].y),
                                  pack_h2(pb[i][0].z, pb[i][0].w),
                                  pack_h2(pb[i][1].x, pb[i][1].y),
                                  pack_h2(pb[i][1].z, pb[i][1].w));
            *reinterpret_cast<uint4*>(&Bs[buf][row][q4]) = ub;
        }
        __syncthreads();

        if (kt + GBK < INF) {
            loadA(kt + GBK);
            loadB(kt + GBK);
        }

        const uint32_t offA = buf ? bufA : 0u;
        const uint32_t offB = buf ? bufB : 0u;
#pragma unroll
        for (int s = 0; s < 2; s++) {
            const uint32_t so = (uint32_t)(s * 8 * 4);
            // A fragments: one x4 per 16-row tile covers the full k16 step
            uint32_t af[2][4];
#pragma unroll
            for (int mt = 0; mt < 2; mt++)
                ldsm_x4(af[mt][0], af[mt][1], af[mt][2], af[mt][3],
                        aAddr[mt] + offA + so);
            // B fragments: one x4 per 2 n8-tiles
            uint32_t bf[8][2];
#pragma unroll
            for (int ng = 0; ng < 4; ng++) {
                uint32_t q0, q1, q2, q3;
                ldsm_x4(q0, q1, q2, q3, bAddr[ng] + offB + so);
                bf[2 * ng][0]     = q0;
                bf[2 * ng + 1][0] = q1;
                bf[2 * ng][1]     = q2;
                bf[2 * ng + 1][1] = q3;
            }
#pragma unroll
            for (int nt = 0; nt < 8; nt++)
#pragma unroll
                for (int mt = 0; mt < 2; mt++)
                    mma_f16(acc[mt][nt], af[mt], bf[nt]);
        }
        buf ^= 1;
    }

    // store fp32 to g_cat; bases cols additionally as half2
#pragma unroll
    for (int mt = 0; mt < 2; mt++) {
#pragma unroll
        for (int nt = 0; nt < 8; nt++) {
            int row = m0 + wm * 32 + mt * 16 + lr;
            int col = n0 + wn * 64 + nt * 8 + 2 * lc;
            if (col < NCAT) {
                if (row < M) {
                    float2 v = make_float2(acc[mt][nt][0], acc[mt][nt][1]);
                    *reinterpret_cast<float2*>(g_cat + (size_t)row * NCAT + col) = v;
                    if (col < AGGC)
                        g_bases_h[(size_t)row * 128 + (col >> 1)] = pack_h2(v.x, v.y);
                }
                if (row + 8 < M) {
                    float2 v = make_float2(acc[mt][nt][2], acc[mt][nt][3]);
                    *reinterpret_cast<float2*>(g_cat + (size_t)(row + 8) * NCAT + col) = v;
                    if (col < AGGC)
                        g_bases_h[(size_t)(row + 8) * 128 + (col >> 1)] = pack_h2(v.x, v.y);
                }
            }
        }
    }
}

// ---------- edge scatter: agg[dst] += bases_h[src] * nrm ----------
__device__ __forceinline__ void red_add_v4(float* addr, float a, float b, float c, float d) {
    asm volatile("red.global.add.v4.f32 [%0], {%1, %2, %3, %4};"
                 :: "l"(addr), "f"(a), "f"(b), "f"(c), "f"(d) : "memory");
}

__global__ void scatter_kernel(const int* __restrict__ ei, int E) {
    int w = (blockIdx.x * blockDim.x + threadIdx.x) >> 5;
    if (w >= E) return;
    int lane = threadIdx.x & 31;
    int src = __ldg(ei + w);
    int dst = __ldg(ei + E + w);
    float nrm = __ldg(g_dinv + src) * __ldg(g_dinv + dst);
    const uint2* brow = reinterpret_cast<const uint2*>(g_bases_h + (size_t)src * 128);
    float* arow = g_agg + (size_t)dst * AGGC;
#pragma unroll
    for (int i = 0; i < 2; i++) {
        int q = lane + i * 32;
        uint2 h = __ldg(brow + q);
        float2 f0 = __half22float2(*reinterpret_cast<__half2*>(&h.x));
        float2 f1 = __half22float2(*reinterpret_cast<__half2*>(&h.y));
        red_add_v4(arow + q * 4, f0.x * nrm, f0.y * nrm, f1.x * nrm, f1.y * nrm);
    }
}

// ---------- combine: einsum + biases + residual + LayerNorm + ReLU ----------
__global__ __launch_bounds__(128)
void combine_kernel(const float* __restrict__ b_comb,
                    const float* __restrict__ conv_bias,
                    const float* __restrict__ b_res,
                    const float* __restrict__ gamma,
                    const float* __restrict__ beta,
                    float* __restrict__ out) {
    int v = blockIdx.x;
    int tid = threadIdx.x;
    __shared__ float sagg[AGGC];
    __shared__ float sw[WCOMB];
    __shared__ float red[8];

    float d = g_dinv[v];
    float d2 = d * d;
    const float* oc = g_cat + (size_t)v * NCAT;
    const float* ag = g_agg + (size_t)v * AGGC;

#pragma unroll
    for (int j = 0; j < 2; j++) {
        int i = tid + j * 128;
        sagg[i] = ag[i] + oc[i] * d2;
    }
    if (tid < WCOMB) sw[tid] = oc[AGGC + tid] + b_comb[tid];
    __syncthreads();

    float val[4];
    float s = 0.f, sq = 0.f;
#pragma unroll
    for (int j = 0; j < 4; j++) {
        int c = tid + j * 128;
        int h = c >> 6, f = c & 63;
        const float* wv = &sw[h * 4];
        float a = wv[0] * sagg[f]
                + wv[1] * sagg[64 + f]
                + wv[2] * sagg[128 + f]
                + wv[3] * sagg[192 + f];
        a += conv_bias[c] + oc[AGGC + WCOMB + c] + b_res[c];
        val[j] = a;
        s += a;
        sq += a * a;
    }
#pragma unroll
    for (int o = 16; o > 0; o >>= 1) {
        s  += __shfl_xor_sync(0xffffffffu, s, o);
        sq += __shfl_xor_sync(0xffffffffu, sq, o);
    }
    if ((tid & 31) == 0) { red[tid >> 5] = s; red[4 + (tid >> 5)] = sq; }
    __syncthreads();
    s  = red[0] + red[1] + red[2] + red[3];
    sq = red[4] + red[5] + red[6] + red[7];
    float mean = s * (1.f / OUTF);
    float var  = sq * (1.f / OUTF) - mean * mean;
    float rstd = rsqrtf(var + LNEPS);
#pragma unroll
    for (int j = 0; j < 4; j++) {
        int c = tid + j * 128;
        float o = (val[j] - mean) * rstd * gamma[c] + beta[c];
        out[(size_t)v * OUTF + c] = fmaxf(o, 0.f);
    }
}

extern "C" void kernel_launch(void* const* d_in, const int* in_sizes, int n_in,
                              void* d_out, int out_size) {
    const float* x     = (const float*)d_in[0];
    const int*   ei    = (const int*)  d_in[1];
    const float* Wb    = (const float*)d_in[2];
    const float* Wc    = (const float*)d_in[3];
    const float* bcomb = (const float*)d_in[4];
    const float* cbias = (const float*)d_in[5];
    const float* Wr    = (const float*)d_in[6];
    const float* bres  = (const float*)d_in[7];
    const float* gamma = (const float*)d_in[8];
    const float* beta  = (const float*)d_in[9];
    float* out = (float*)d_out;

    const int N = in_sizes[0] / INF;
    const int E = in_sizes[1] / 2;

    // 1. zero agg + deg
    {
        int nAgg4 = (N * AGGC) / 4;
        zero_kernel<<<(nAgg4 + 255) / 256, 256>>>(nAgg4, N);
    }
    // 2. concat + transpose weights
    concatw_kernel<<<(INF * NCAT + 255) / 256, 256>>>(Wb, Wc, Wr);
    // 3. degrees
    deg_kernel<<<(E + 255) / 256, 256>>>(ei, E);
    dinv_kernel<<<(N + 255) / 256, 256>>>(N);
    // 4. fused GEMM (FP16 tensor cores, ldmatrix fragments, double-buffered)
    {
        dim3 grid((NCAT + GBN - 1) / GBN, (N + GBM - 1) / GBM);
        f16gemm_kernel<<<grid, 256>>>(x, N);
    }
    // 5. edge scatter (fp16 bases reads, v4 reduction atomics)
    {
        long long threads = (long long)E * 32;
        int blocks = (int)((threads + 255) / 256);
        scatter_kernel<<<blocks, 256>>>(ei, E);
    }
    // 6. combine + LayerNorm + ReLU
    combine_kernel<<<N, 128>>>(bcomb, cbias, bres, gamma, beta, out);
}

// round 13
// speedup vs baseline: 1.2027x; 1.0009x over previous
#include <cuda_runtime.h>
#include <cuda_fp16.h>
#include <cstdint>

// Problem constants (fixed shapes for this problem instance)
#define NODES   50000
#define EDGES   800000
#define INF     512
#define OUTF    512
#define HEADS   8
#define NBASES  4
#define FHD     64          // OUTF/HEADS
#define AGGC    256         // NBASES*FHD
#define WCOMB   32          // HEADS*NBASES
#define NCAT    800         // 256 + 32 + 512 concatenated GEMM output cols
#define LNEPS   1e-5f

// ---------- device scratch (static allocation; no cudaMalloc allowed) ----------
__device__ uint32_t g_wh[(size_t)NCAT * 256];         // fp16 weights, [c][kpair] (~1.6MB)
__device__ uint32_t g_xh[(size_t)NODES * 256];        // fp16 x, [n][kpair] (~51MB)
__device__ float    g_cat[(size_t)NODES * NCAT];      // x @ Wcat  [N,800]  (~160MB)
__device__ uint32_t g_bases_h[(size_t)NODES * 128];   // bases as half2 [N,128] (~25.6MB)
__device__ float    g_agg[(size_t)NODES * AGGC];      // symnorm aggregation [N,256] (~51MB)
__device__ float    g_dinv[NODES];
__device__ int      g_deg[NODES];

// ---------- zero agg + deg ----------
__global__ void zero_kernel(int nAgg4, int nDeg) {
    int i = blockIdx.x * blockDim.x + threadIdx.x;
    if (i < nAgg4) reinterpret_cast<float4*>(g_agg)[i] = make_float4(0.f, 0.f, 0.f, 0.f);
    if (i < nDeg)  g_deg[i] = 0;
}

__device__ __forceinline__ uint32_t pack_h2(float lo, float hi) {
    __half2 h = __floats2half2_rn(lo, hi);
    return *reinterpret_cast<uint32_t*>(&h);
}

// ---------- concat + transpose weights directly to fp16 [c][kpair] ----------
__global__ void concatw_kernel(const float* __restrict__ Wb,
                               const float* __restrict__ Wc,
                               const float* __restrict__ Wr) {
    int i = blockIdx.x * blockDim.x + threadIdx.x;
    if (i >= NCAT * 256) return;
    int kp = i & 255;            // k pair index
    int c  = i >> 8;
    int k0 = 2 * kp, k1 = 2 * kp + 1;
    float v0, v1;
    if (c < AGGC) {
        v0 = Wb[k0 * AGGC + c]; v1 = Wb[k1 * AGGC + c];
    } else if (c < AGGC + WCOMB) {
        v0 = Wc[k0 * WCOMB + (c - AGGC)]; v1 = Wc[k1 * WCOMB + (c - AGGC)];
    } else {
        v0 = Wr[k0 * OUTF + (c - AGGC - WCOMB)]; v1 = Wr[k1 * OUTF + (c - AGGC - WCOMB)];
    }
    g_wh[(size_t)c * 256 + kp] = pack_h2(v0, v1);
}

// ---------- x -> fp16 pack ----------
__global__ void xh_kernel(const float* __restrict__ x, int total) {
    int i = blockIdx.x * blockDim.x + threadIdx.x;
    if (i >= total) return;
    float2 v = *reinterpret_cast<const float2*>(x + 2 * (size_t)i);
    g_xh[i] = pack_h2(v.x, v.y);
}

// ---------- degree count ----------
__global__ void deg_kernel(const int* __restrict__ ei, int E) {
    int i = blockIdx.x * blockDim.x + threadIdx.x;
    if (i < E) atomicAdd(&g_deg[ei[E + i]], 1);
}

__global__ void dinv_kernel(int n) {
    int i = blockIdx.x * blockDim.x + threadIdx.x;
    if (i < n) g_dinv[i] = rsqrtf((float)(g_deg[i] + 1));  // +1 self loop
}

// ---------- FP16 tensor-core GEMM (ldmatrix + cp.async double buffer) ----------
__device__ __forceinline__ void mma_f16(float* d, const uint32_t* a, const uint32_t* b) {
    asm volatile("mma.sync.aligned.m16n8k16.row.col.f32.f16.f16.f32 "
                 "{%0,%1,%2,%3},{%4,%5,%6,%7},{%8,%9},{%0,%1,%2,%3};"
                 : "+f"(d[0]), "+f"(d[1]), "+f"(d[2]), "+f"(d[3])
                 : "r"(a[0]), "r"(a[1]), "r"(a[2]), "r"(a[3]),
                   "r"(b[0]), "r"(b[1]));
}

__device__ __forceinline__ void ldsm_x4(uint32_t& r0, uint32_t& r1,
                                        uint32_t& r2, uint32_t& r3, uint32_t addr) {
    asm volatile("ldmatrix.sync.aligned.m8n8.x4.shared.b16 {%0,%1,%2,%3}, [%4];"
                 : "=r"(r0), "=r"(r1), "=r"(r2), "=r"(r3) : "r"(addr));
}

__device__ __forceinline__ uint32_t smem_u32(const void* p) {
    uint32_t a;
    asm("{ .reg .u64 t; cvta.to.shared.u64 t, %1; cvt.u32.u64 %0, t; }" : "=r"(a) : "l"(p));
    return a;
}

__device__ __forceinline__ void cp16(uint32_t dst, const void* src, int srcBytes) {
    asm volatile("cp.async.cg.shared.global [%0], [%1], 16, %2;"
                 :: "r"(dst), "l"(src), "r"(srcBytes) : "memory");
}

#define GBM 128
#define GBN 128
#define GBK 32
#define HP  20    // row pitch in words (16 used + 4 pad) -> conflict-free LDSM

__global__ __launch_bounds__(256, 2)
void f16gemm_kernel(int M) {
    __shared__ uint32_t As[2][GBM][HP];
    __shared__ uint32_t Bs[2][GBN][HP];
    const int t    = threadIdx.x;
    const int wid  = t >> 5;
    const int lane = t & 31;
    const int wm   = wid & 3;
    const int wn   = wid >> 2;
    const int lr   = lane >> 2;
    const int lc   = lane & 3;
    const int m0   = blockIdx.y * GBM;
    const int n0   = blockIdx.x * GBN;

    // ldmatrix per-lane addressing
    const int lrow = (lane & 7) + ((lane >> 3) & 1) * 8;
    const int lcol = (lane >> 4) * 4;
    const uint32_t sbA = smem_u32(&As[0][0][0]);
    const uint32_t sbB = smem_u32(&Bs[0][0][0]);
    uint32_t aAddr[2], bAddr[4];
#pragma unroll
    for (int mt = 0; mt < 2; mt++)
        aAddr[mt] = sbA + (uint32_t)(((wm * 32 + mt * 16 + lrow) * HP + lcol) * 4);
#pragma unroll
    for (int ng = 0; ng < 4; ng++)
        bAddr[ng] = sbB + (uint32_t)(((wn * 64 + ng * 16 + lrow) * HP + lcol) * 4);
    const uint32_t bufA = (uint32_t)(GBM * HP * 4);
    const uint32_t bufB = (uint32_t)(GBN * HP * 4);

    // staging decomposition: 512 16B-chunks per operand, 2 per thread
    const int srow = t >> 2;          // 0..63 per quarter-... wait: f>>2 with f=t+i*256
    (void)srow;

    float acc[2][8][4];
#pragma unroll
    for (int mt = 0; mt < 2; mt++)
#pragma unroll
        for (int nt = 0; nt < 8; nt++)
#pragma unroll
            for (int r = 0; r < 4; r++) acc[mt][nt][r] = 0.f;

    auto issue = [&](int kt, int b) {
        const int kw = kt >> 1;       // word offset within row
#pragma unroll
        for (int i = 0; i < 2; i++) {
            int f   = t + i * 256;    // 0..511
            int row = f >> 2;         // 0..127
            int c16 = (f & 3) * 4;    // word group
            uint32_t dA = smem_u32(&As[b][row][c16]);
            const uint32_t* sA = g_xh + (size_t)(m0 + row) * 256 + kw + c16;
            cp16(dA, sA, (m0 + row < M) ? 16 : 0);
            uint32_t dB = smem_u32(&Bs[b][row][c16]);
            const uint32_t* sB = g_wh + (size_t)(n0 + row) * 256 + kw + c16;
            cp16(dB, sB, (n0 + row < NCAT) ? 16 : 0);
        }
        asm volatile("cp.async.commit_group;" ::: "memory");
    };

    issue(0, 0);
    int buf = 0;

    for (int kt = 0; kt < INF; kt += GBK) {
        const bool more = (kt + GBK < INF);
        if (more) issue(kt + GBK, buf ^ 1);
        if (more) asm volatile("cp.async.wait_group 1;" ::: "memory");
        else      asm volatile("cp.async.wait_group 0;" ::: "memory");
        __syncthreads();

        const uint32_t offA = buf ? bufA : 0u;
        const uint32_t offB = buf ? bufB : 0u;
#pragma unroll
        for (int s = 0; s < 2; s++) {
            const uint32_t so = (uint32_t)(s * 8 * 4);
            uint32_t af[2][4];
#pragma unroll
            for (int mt = 0; mt < 2; mt++)
                ldsm_x4(af[mt][0], af[mt][1], af[mt][2], af[mt][3],
                        aAddr[mt] + offA + so);
            uint32_t bf[8][2];
#pragma unroll
            for (int ng = 0; ng < 4; ng++) {
                uint32_t q0, q1, q2, q3;
                ldsm_x4(q0, q1, q2, q3, bAddr[ng] + offB + so);
                bf[2 * ng][0]     = q0;
                bf[2 * ng + 1][0] = q1;
                bf[2 * ng][1]     = q2;
                bf[2 * ng + 1][1] = q3;
            }
#pragma unroll
            for (int nt = 0; nt < 8; nt++)
#pragma unroll
                for (int mt = 0; mt < 2; mt++)
                    mma_f16(acc[mt][nt], af[mt], bf[nt]);
        }
        __syncthreads();   // compute done before next issue overwrites this buf
        buf ^= 1;
    }

    // store fp32 to g_cat; bases cols additionally as half2
#pragma unroll
    for (int mt = 0; mt < 2; mt++) {
#pragma unroll
        for (int nt = 0; nt < 8; nt++) {
            int row = m0 + wm * 32 + mt * 16 + lr;
            int col = n0 + wn * 64 + nt * 8 + 2 * lc;
            if (col < NCAT) {
                if (row < M) {
                    float2 v = make_float2(acc[mt][nt][0], acc[mt][nt][1]);
                    *reinterpret_cast<float2*>(g_cat + (size_t)row * NCAT + col) = v;
                    if (col < AGGC)
                        g_bases_h[(size_t)row * 128 + (col >> 1)] = pack_h2(v.x, v.y);
                }
                if (row + 8 < M) {
                    float2 v = make_float2(acc[mt][nt][2], acc[mt][nt][3]);
                    *reinterpret_cast<float2*>(g_cat + (size_t)(row + 8) * NCAT + col) = v;
                    if (col < AGGC)
                        g_bases_h[(size_t)(row + 8) * 128 + (col >> 1)] = pack_h2(v.x, v.y);
                }
            }
        }
    }
}

// ---------- edge scatter: agg[dst] += bases_h[src] * nrm ----------
__device__ __forceinline__ void red_add_v4(float* addr, float a, float b, float c, float d) {
    asm volatile("red.global.add.v4.f32 [%0], {%1, %2, %3, %4};"
                 :: "l"(addr), "f"(a), "f"(b), "f"(c), "f"(d) : "memory");
}

__global__ void scatter_kernel(const int* __restrict__ ei, int E) {
    int w = (blockIdx.x * blockDim.x + threadIdx.x) >> 5;
    if (w >= E) return;
    int lane = threadIdx.x & 31;
    int src = __ldg(ei + w);
    int dst = __ldg(ei + E + w);
    float nrm = __ldg(g_dinv + src) * __ldg(g_dinv + dst);
    const uint2* brow = reinterpret_cast<const uint2*>(g_bases_h + (size_t)src * 128);
    float* arow = g_agg + (size_t)dst * AGGC;
#pragma unroll
    for (int i = 0; i < 2; i++) {
        int q = lane + i * 32;
        uint2 h = __ldg(brow + q);
        float2 f0 = __half22float2(*reinterpret_cast<__half2*>(&h.x));
        float2 f1 = __half22float2(*reinterpret_cast<__half2*>(&h.y));
        red_add_v4(arow + q * 4, f0.x * nrm, f0.y * nrm, f1.x * nrm, f1.y * nrm);
    }
}

// ---------- combine: einsum + biases + residual + LayerNorm + ReLU ----------
__global__ __launch_bounds__(128)
void combine_kernel(const float* __restrict__ b_comb,
                    const float* __restrict__ conv_bias,
                    const float* __restrict__ b_res,
                    const float* __restrict__ gamma,
                    const float* __restrict__ beta,
                    float* __restrict__ out) {
    int v = blockIdx.x;
    int tid = threadIdx.x;
    __shared__ float sagg[AGGC];
    __shared__ float sw[WCOMB];
    __shared__ float red[8];

    float d = g_dinv[v];
    float d2 = d * d;
    const float* oc = g_cat + (size_t)v * NCAT;
    const float* ag = g_agg + (size_t)v * AGGC;

#pragma unroll
    for (int j = 0; j < 2; j++) {
        int i = tid + j * 128;
        sagg[i] = ag[i] + oc[i] * d2;
    }
    if (tid < WCOMB) sw[tid] = oc[AGGC + tid] + b_comb[tid];
    __syncthreads();

    float val[4];
    float s = 0.f, sq = 0.f;
#pragma unroll
    for (int j = 0; j < 4; j++) {
        int c = tid + j * 128;
        int h = c >> 6, f = c & 63;
        const float* wv = &sw[h * 4];
        float a = wv[0] * sagg[f]
                + wv[1] * sagg[64 + f]
                + wv[2] * sagg[128 + f]
                + wv[3] * sagg[192 + f];
        a += conv_bias[c] + oc[AGGC + WCOMB + c] + b_res[c];
        val[j] = a;
        s += a;
        sq += a * a;
    }
#pragma unroll
    for (int o = 16; o > 0; o >>= 1) {
        s  += __shfl_xor_sync(0xffffffffu, s, o);
        sq += __shfl_xor_sync(0xffffffffu, sq, o);
    }
    if ((tid & 31) == 0) { red[tid >> 5] = s; red[4 + (tid >> 5)] = sq; }
    __syncthreads();
    s  = red[0] + red[1] + red[2] + red[3];
    sq = red[4] + red[5] + red[6] + red[7];
    float mean = s * (1.f / OUTF);
    float var  = sq * (1.f / OUTF) - mean * mean;
    float rstd = rsqrtf(var + LNEPS);
#pragma unroll
    for (int j = 0; j < 4; j++) {
        int c = tid + j * 128;
        float o = (val[j] - mean) * rstd * gamma[c] + beta[c];
        out[(size_t)v * OUTF + c] = fmaxf(o, 0.f);
    }
}

extern "C" void kernel_launch(void* const* d_in, const int* in_sizes, int n_in,
                              void* d_out, int out_size) {
    const float* x     = (const float*)d_in[0];
    const int*   ei    = (const int*)  d_in[1];
    const float* Wb    = (const float*)d_in[2];
    const float* Wc    = (const float*)d_in[3];
    const float* bcomb = (const float*)d_in[4];
    const float* cbias = (const float*)d_in[5];
    const float* Wr    = (const float*)d_in[6];
    const float* bres  = (const float*)d_in[7];
    const float* gamma = (const float*)d_in[8];
    const float* beta  = (const float*)d_in[9];
    float* out = (float*)d_out;

    const int N = in_sizes[0] / INF;
    const int E = in_sizes[1] / 2;

    // 1. zero agg + deg
    {
        int nAgg4 = (N * AGGC) / 4;
        zero_kernel<<<(nAgg4 + 255) / 256, 256>>>(nAgg4, N);
    }
    // 2. weights -> fp16 [c][kpair]; x -> fp16 [n][kpair]
    concatw_kernel<<<(NCAT * 256 + 255) / 256, 256>>>(Wb, Wc, Wr);
    xh_kernel<<<(N * 256 + 255) / 256, 256>>>(x, N * 256);
    // 3. degrees
    deg_kernel<<<(E + 255) / 256, 256>>>(ei, E);
    dinv_kernel<<<(N + 255) / 256, 256>>>(N);
    // 4. fused GEMM (FP16 tensor cores, cp.async staged, ldmatrix fragments)
    {
        dim3 grid((NCAT + GBN - 1) / GBN, (N + GBM - 1) / GBM);
        f16gemm_kernel<<<grid, 256>>>(N);
    }
    // 5. edge scatter (fp16 bases reads, v4 reduction atomics)
    {
        long long threads = (long long)E * 32;
        int blocks = (int)((threads + 255) / 256);
        scatter_kernel<<<blocks, 256>>>(ei, E);
    }
    // 6. combine + LayerNorm + ReLU
    combine_kernel<<<N, 128>>>(bcomb, cbias, bres, gamma, beta, out);
}

// round 14
// speedup vs baseline: 1.2359x; 1.0276x over previous
#include <cuda_runtime.h>
#include <cuda_fp16.h>
#include <cstdint>

// Problem constants (fixed shapes for this problem instance)
#define NODES   50000
#define EDGES   800000
#define INF     512
#define OUTF    512
#define HEADS   8
#define NBASES  4
#define FHD     64          // OUTF/HEADS
#define AGGC    256         // NBASES*FHD
#define WCOMB   32          // HEADS*NBASES
#define NCAT    800         // 256 + 32 + 512 concatenated GEMM output cols
#define LNEPS   1e-5f

// ---------- device scratch (static allocation; no cudaMalloc allowed) ----------
__device__ uint32_t g_wh[(size_t)NCAT * 256];         // fp16 weights, [c][kpair] (~1.6MB)
__device__ uint32_t g_xh[(size_t)NODES * 256];        // fp16 x, [n][kpair] (~51MB)
__device__ float    g_cat[(size_t)NODES * NCAT];      // cols 256..799 used (~160MB alloc)
__device__ uint32_t g_bases_h[(size_t)NODES * 128];   // bases as half2 [N,128] (~25.6MB)
__device__ float    g_agg[(size_t)NODES * AGGC];      // symnorm aggregation [N,256] (~51MB)
__device__ float    g_dinv[NODES];
__device__ int      g_deg[NODES];

// ---------- zero agg + deg ----------
__global__ void zero_kernel(int nAgg4, int nDeg) {
    int i = blockIdx.x * blockDim.x + threadIdx.x;
    if (i < nAgg4) reinterpret_cast<float4*>(g_agg)[i] = make_float4(0.f, 0.f, 0.f, 0.f);
    if (i < nDeg)  g_deg[i] = 0;
}

__device__ __forceinline__ uint32_t pack_h2(float lo, float hi) {
    __half2 h = __floats2half2_rn(lo, hi);
    return *reinterpret_cast<uint32_t*>(&h);
}

// ---------- concat + transpose weights directly to fp16 [c][kpair] ----------
__global__ void concatw_kernel(const float* __restrict__ Wb,
                               const float* __restrict__ Wc,
                               const float* __restrict__ Wr) {
    int i = blockIdx.x * blockDim.x + threadIdx.x;
    if (i >= NCAT * 256) return;
    int kp = i & 255;            // k pair index
    int c  = i >> 8;
    int k0 = 2 * kp, k1 = 2 * kp + 1;
    float v0, v1;
    if (c < AGGC) {
        v0 = Wb[k0 * AGGC + c]; v1 = Wb[k1 * AGGC + c];
    } else if (c < AGGC + WCOMB) {
        v0 = Wc[k0 * WCOMB + (c - AGGC)]; v1 = Wc[k1 * WCOMB + (c - AGGC)];
    } else {
        v0 = Wr[k0 * OUTF + (c - AGGC - WCOMB)]; v1 = Wr[k1 * OUTF + (c - AGGC - WCOMB)];
    }
    g_wh[(size_t)c * 256 + kp] = pack_h2(v0, v1);
}

// ---------- x -> fp16 pack ----------
__global__ void xh_kernel(const float* __restrict__ x, int total) {
    int i = blockIdx.x * blockDim.x + threadIdx.x;
    if (i >= total) return;
    float2 v = *reinterpret_cast<const float2*>(x + 2 * (size_t)i);
    g_xh[i] = pack_h2(v.x, v.y);
}

// ---------- degree count ----------
__global__ void deg_kernel(const int* __restrict__ ei, int E) {
    int i = blockIdx.x * blockDim.x + threadIdx.x;
    if (i < E) atomicAdd(&g_deg[ei[E + i]], 1);
}

__global__ void dinv_kernel(int n) {
    int i = blockIdx.x * blockDim.x + threadIdx.x;
    if (i < n) g_dinv[i] = rsqrtf((float)(g_deg[i] + 1));  // +1 self loop
}

// ---------- FP16 tensor-core GEMM (ldmatrix + cp.async double buffer) ----------
__device__ __forceinline__ void mma_f16(float* d, const uint32_t* a, const uint32_t* b) {
    asm volatile("mma.sync.aligned.m16n8k16.row.col.f32.f16.f16.f32 "
                 "{%0,%1,%2,%3},{%4,%5,%6,%7},{%8,%9},{%0,%1,%2,%3};"
                 : "+f"(d[0]), "+f"(d[1]), "+f"(d[2]), "+f"(d[3])
                 : "r"(a[0]), "r"(a[1]), "r"(a[2]), "r"(a[3]),
                   "r"(b[0]), "r"(b[1]));
}

__device__ __forceinline__ void ldsm_x4(uint32_t& r0, uint32_t& r1,
                                        uint32_t& r2, uint32_t& r3, uint32_t addr) {
    asm volatile("ldmatrix.sync.aligned.m8n8.x4.shared.b16 {%0,%1,%2,%3}, [%4];"
                 : "=r"(r0), "=r"(r1), "=r"(r2), "=r"(r3) : "r"(addr));
}

__device__ __forceinline__ uint32_t smem_u32(const void* p) {
    uint32_t a;
    asm("{ .reg .u64 t; cvta.to.shared.u64 t, %1; cvt.u32.u64 %0, t; }" : "=r"(a) : "l"(p));
    return a;
}

__device__ __forceinline__ void cp16(uint32_t dst, const void* src, int srcBytes) {
    asm volatile("cp.async.cg.shared.global [%0], [%1], 16, %2;"
                 :: "r"(dst), "l"(src), "r"(srcBytes) : "memory");
}

#define GBM 128
#define GBN 128
#define GBK 32
#define HP  20    // row pitch in words (16 used + 4 pad) -> conflict-free LDSM

__global__ __launch_bounds__(256, 2)
void f16gemm_kernel(int M) {
    __shared__ uint32_t As[2][GBM][HP];
    __shared__ uint32_t Bs[2][GBN][HP];
    const int t    = threadIdx.x;
    const int wid  = t >> 5;
    const int lane = t & 31;
    const int wm   = wid & 3;
    const int wn   = wid >> 2;
    const int lr   = lane >> 2;
    const int lc   = lane & 3;
    const int m0   = blockIdx.y * GBM;
    const int n0   = blockIdx.x * GBN;

    const int lrow = (lane & 7) + ((lane >> 3) & 1) * 8;
    const int lcol = (lane >> 4) * 4;
    const uint32_t sbA = smem_u32(&As[0][0][0]);
    const uint32_t sbB = smem_u32(&Bs[0][0][0]);
    uint32_t aAddr[2], bAddr[4];
#pragma unroll
    for (int mt = 0; mt < 2; mt++)
        aAddr[mt] = sbA + (uint32_t)(((wm * 32 + mt * 16 + lrow) * HP + lcol) * 4);
#pragma unroll
    for (int ng = 0; ng < 4; ng++)
        bAddr[ng] = sbB + (uint32_t)(((wn * 64 + ng * 16 + lrow) * HP + lcol) * 4);
    const uint32_t bufA = (uint32_t)(GBM * HP * 4);
    const uint32_t bufB = (uint32_t)(GBN * HP * 4);

    float acc[2][8][4];
#pragma unroll
    for (int mt = 0; mt < 2; mt++)
#pragma unroll
        for (int nt = 0; nt < 8; nt++)
#pragma unroll
            for (int r = 0; r < 4; r++) acc[mt][nt][r] = 0.f;

    auto issue = [&](int kt, int b) {
        const int kw = kt >> 1;
#pragma unroll
        for (int i = 0; i < 2; i++) {
            int f   = t + i * 256;
            int row = f >> 2;
            int c16 = (f & 3) * 4;
            uint32_t dA = smem_u32(&As[b][row][c16]);
            const uint32_t* sA = g_xh + (size_t)(m0 + row) * 256 + kw + c16;
            cp16(dA, sA, (m0 + row < M) ? 16 : 0);
            uint32_t dB = smem_u32(&Bs[b][row][c16]);
            const uint32_t* sB = g_wh + (size_t)(n0 + row) * 256 + kw + c16;
            cp16(dB, sB, (n0 + row < NCAT) ? 16 : 0);
        }
        asm volatile("cp.async.commit_group;" ::: "memory");
    };

    issue(0, 0);
    int buf = 0;

    for (int kt = 0; kt < INF; kt += GBK) {
        const bool more = (kt + GBK < INF);
        if (more) issue(kt + GBK, buf ^ 1);
        if (more) asm volatile("cp.async.wait_group 1;" ::: "memory");
        else      asm volatile("cp.async.wait_group 0;" ::: "memory");
        __syncthreads();

        const uint32_t offA = buf ? bufA : 0u;
        const uint32_t offB = buf ? bufB : 0u;
#pragma unroll
        for (int s = 0; s < 2; s++) {
            const uint32_t so = (uint32_t)(s * 8 * 4);
            uint32_t af[2][4];
#pragma unroll
            for (int mt = 0; mt < 2; mt++)
                ldsm_x4(af[mt][0], af[mt][1], af[mt][2], af[mt][3],
                        aAddr[mt] + offA + so);
            uint32_t bf[8][2];
#pragma unroll
            for (int ng = 0; ng < 4; ng++) {
                uint32_t q0, q1, q2, q3;
                ldsm_x4(q0, q1, q2, q3, bAddr[ng] + offB + so);
                bf[2 * ng][0]     = q0;
                bf[2 * ng + 1][0] = q1;
                bf[2 * ng][1]     = q2;
                bf[2 * ng + 1][1] = q3;
            }
#pragma unroll
            for (int nt = 0; nt < 8; nt++)
#pragma unroll
                for (int mt = 0; mt < 2; mt++)
                    mma_f16(acc[mt][nt], af[mt], bf[nt]);
        }
        __syncthreads();
        buf ^= 1;
    }

    // store: bases block (n-blocks 0..1) -> fp16 ONLY; rest -> fp32 g_cat
    const bool isBases = (n0 < AGGC);   // block-uniform
#pragma unroll
    for (int mt = 0; mt < 2; mt++) {
#pragma unroll
        for (int nt = 0; nt < 8; nt++) {
            int row = m0 + wm * 32 + mt * 16 + lr;
            int col = n0 + wn * 64 + nt * 8 + 2 * lc;
            if (isBases) {
                if (row < M)
                    g_bases_h[(size_t)row * 128 + (col >> 1)] =
                        pack_h2(acc[mt][nt][0], acc[mt][nt][1]);
                if (row + 8 < M)
                    g_bases_h[(size_t)(row + 8) * 128 + (col >> 1)] =
                        pack_h2(acc[mt][nt][2], acc[mt][nt][3]);
            } else if (col < NCAT) {
                if (row < M) {
                    float2 v = make_float2(acc[mt][nt][0], acc[mt][nt][1]);
                    *reinterpret_cast<float2*>(g_cat + (size_t)row * NCAT + col) = v;
                }
                if (row + 8 < M) {
                    float2 v = make_float2(acc[mt][nt][2], acc[mt][nt][3]);
                    *reinterpret_cast<float2*>(g_cat + (size_t)(row + 8) * NCAT + col) = v;
                }
            }
        }
    }
}

// ---------- edge scatter: agg[dst] += bases_h[src] * nrm ----------
__device__ __forceinline__ void red_add_v4(float* addr, float a, float b, float c, float d) {
    asm volatile("red.global.add.v4.f32 [%0], {%1, %2, %3, %4};"
                 :: "l"(addr), "f"(a), "f"(b), "f"(c), "f"(d) : "memory");
}

__global__ void scatter_kernel(const int* __restrict__ ei, int E) {
    int w = (blockIdx.x * blockDim.x + threadIdx.x) >> 5;
    if (w >= E) return;
    int lane = threadIdx.x & 31;
    int src = __ldg(ei + w);
    int dst = __ldg(ei + E + w);
    float nrm = __ldg(g_dinv + src) * __ldg(g_dinv + dst);
    const uint2* brow = reinterpret_cast<const uint2*>(g_bases_h + (size_t)src * 128);
    float* arow = g_agg + (size_t)dst * AGGC;
#pragma unroll
    for (int i = 0; i < 2; i++) {
        int q = lane + i * 32;
        uint2 h = __ldg(brow + q);
        float2 f0 = __half22float2(*reinterpret_cast<__half2*>(&h.x));
        float2 f1 = __half22float2(*reinterpret_cast<__half2*>(&h.y));
        red_add_v4(arow + q * 4, f0.x * nrm, f0.y * nrm, f1.x * nrm, f1.y * nrm);
    }
}

// ---------- combine: einsum + biases + residual + LayerNorm + ReLU ----------
__global__ __launch_bounds__(128)
void combine_kernel(const float* __restrict__ b_comb,
                    const float* __restrict__ conv_bias,
                    const float* __restrict__ b_res,
                    const float* __restrict__ gamma,
                    const float* __restrict__ beta,
                    float* __restrict__ out) {
    int v = blockIdx.x;
    int tid = threadIdx.x;
    __shared__ float sagg[AGGC];
    __shared__ float sw[WCOMB];
    __shared__ float red[8];

    float d = g_dinv[v];
    float d2 = d * d;
    const float* oc = g_cat + (size_t)v * NCAT;
    const float* ag = g_agg + (size_t)v * AGGC;

    // agg row + self-loop term (bases from fp16 copy; validated in R10)
    {
        uint32_t h = g_bases_h[(size_t)v * 128 + tid];
        float2 bf = __half22float2(*reinterpret_cast<__half2*>(&h));
        float2 av = *reinterpret_cast<const float2*>(ag + 2 * tid);
        sagg[2 * tid]     = av.x + bf.x * d2;
        sagg[2 * tid + 1] = av.y + bf.y * d2;
    }
    if (tid < WCOMB) sw[tid] = oc[AGGC + tid] + b_comb[tid];
    __syncthreads();

    float val[4];
    float s = 0.f, sq = 0.f;
#pragma unroll
    for (int j = 0; j < 4; j++) {
        int c = tid + j * 128;
        int h = c >> 6, f = c & 63;
        const float* wv = &sw[h * 4];
        float a = wv[0] * sagg[f]
                + wv[1] * sagg[64 + f]
                + wv[2] * sagg[128 + f]
                + wv[3] * sagg[192 + f];
        a += conv_bias[c] + oc[AGGC + WCOMB + c] + b_res[c];
        val[j] = a;
        s += a;
        sq += a * a;
    }
#pragma unroll
    for (int o = 16; o > 0; o >>= 1) {
        s  += __shfl_xor_sync(0xffffffffu, s, o);
        sq += __shfl_xor_sync(0xffffffffu, sq, o);
    }
    if ((tid & 31) == 0) { red[tid >> 5] = s; red[4 + (tid >> 5)] = sq; }
    __syncthreads();
    s  = red[0] + red[1] + red[2] + red[3];
    sq = red[4] + red[5] + red[6] + red[7];
    float mean = s * (1.f / OUTF);
    float var  = sq * (1.f / OUTF) - mean * mean;
    float rstd = rsqrtf(var + LNEPS);
#pragma unroll
    for (int j = 0; j < 4; j++) {
        int c = tid + j * 128;
        float o = (val[j] - mean) * rstd * gamma[c] + beta[c];
        out[(size_t)v * OUTF + c] = fmaxf(o, 0.f);
    }
}

extern "C" void kernel_launch(void* const* d_in, const int* in_sizes, int n_in,
                              void* d_out, int out_size) {
    const float* x     = (const float*)d_in[0];
    const int*   ei    = (const int*)  d_in[1];
    const float* Wb    = (const float*)d_in[2];
    const float* Wc    = (const float*)d_in[3];
    const float* bcomb = (const float*)d_in[4];
    const float* cbias = (const float*)d_in[5];
    const float* Wr    = (const float*)d_in[6];
    const float* bres  = (const float*)d_in[7];
    const float* gamma = (const float*)d_in[8];
    const float* beta  = (const float*)d_in[9];
    float* out = (float*)d_out;

    const int N = in_sizes[0] / INF;
    const int E = in_sizes[1] / 2;

    // 1. zero agg + deg
    {
        int nAgg4 = (N * AGGC) / 4;
        zero_kernel<<<(nAgg4 + 255) / 256, 256>>>(nAgg4, N);
    }
    // 2. weights -> fp16 [c][kpair]; x -> fp16 [n][kpair]
    concatw_kernel<<<(NCAT * 256 + 255) / 256, 256>>>(Wb, Wc, Wr);
    xh_kernel<<<(N * 256 + 255) / 256, 256>>>(x, N * 256);
    // 3. degrees
    deg_kernel<<<(E + 255) / 256, 256>>>(ei, E);
    dinv_kernel<<<(N + 255) / 256, 256>>>(N);
    // 4. fused GEMM (FP16 tensor cores, cp.async staged, ldmatrix fragments)
    {
        dim3 grid((NCAT + GBN - 1) / GBN, (N + GBM - 1) / GBM);
        f16gemm_kernel<<<grid, 256>>>(N);
    }
    // 5. edge scatter (fp16 bases reads, v4 reduction atomics)
    {
        long long threads = (long long)E * 32;
        int blocks = (int)((threads + 255) / 256);
        scatter_kernel<<<blocks, 256>>>(ei, E);
    }
    // 6. combine + LayerNorm + ReLU
    combine_kernel<<<N, 128>>>(bcomb, cbias, bres, gamma, beta, out);
}

// round 15
// speedup vs baseline: 1.2519x; 1.0130x over previous
#include <cuda_runtime.h>
#include <cuda_fp16.h>
#include <cstdint>

// Problem constants (fixed shapes for this problem instance)
#define NODES   50000
#define EDGES   800000
#define INF     512
#define OUTF    512
#define HEADS   8
#define NBASES  4
#define FHD     64          // OUTF/HEADS
#define AGGC    256         // NBASES*FHD
#define WCOMB   32          // HEADS*NBASES
#define NCAT    800         // 256 + 32 + 512 concatenated GEMM output cols
#define RESTW   272         // (WCOMB+OUTF)/2 half2 words per node
#define LNEPS   1e-5f

// ---------- device scratch (static allocation; no cudaMalloc allowed) ----------
__device__ uint32_t g_wh[(size_t)NCAT * 256];         // fp16 weights, [c][kpair] (~1.6MB)
__device__ uint32_t g_xh[(size_t)NODES * 256];        // fp16 x, [n][kpair] (~51MB)
__device__ uint32_t g_rest_h[(size_t)NODES * RESTW];  // fp16 comb+res [N,272] (~54MB)
__device__ uint32_t g_bases_h[(size_t)NODES * 128];   // bases as half2 [N,128] (~25.6MB)
__device__ float    g_agg[(size_t)NODES * AGGC];      // symnorm aggregation [N,256] (~51MB)
__device__ float    g_dinv[NODES];
__device__ int      g_deg[NODES];

// ---------- zero agg + deg ----------
__global__ void zero_kernel(int nAgg4, int nDeg) {
    int i = blockIdx.x * blockDim.x + threadIdx.x;
    if (i < nAgg4) reinterpret_cast<float4*>(g_agg)[i] = make_float4(0.f, 0.f, 0.f, 0.f);
    if (i < nDeg)  g_deg[i] = 0;
}

__device__ __forceinline__ uint32_t pack_h2(float lo, float hi) {
    __half2 h = __floats2half2_rn(lo, hi);
    return *reinterpret_cast<uint32_t*>(&h);
}

// ---------- concat + transpose weights directly to fp16 [c][kpair] ----------
__global__ void concatw_kernel(const float* __restrict__ Wb,
                               const float* __restrict__ Wc,
                               const float* __restrict__ Wr) {
    int i = blockIdx.x * blockDim.x + threadIdx.x;
    if (i >= NCAT * 256) return;
    int kp = i & 255;
    int c  = i >> 8;
    int k0 = 2 * kp, k1 = 2 * kp + 1;
    float v0, v1;
    if (c < AGGC) {
        v0 = Wb[k0 * AGGC + c]; v1 = Wb[k1 * AGGC + c];
    } else if (c < AGGC + WCOMB) {
        v0 = Wc[k0 * WCOMB + (c - AGGC)]; v1 = Wc[k1 * WCOMB + (c - AGGC)];
    } else {
        v0 = Wr[k0 * OUTF + (c - AGGC - WCOMB)]; v1 = Wr[k1 * OUTF + (c - AGGC - WCOMB)];
    }
    g_wh[(size_t)c * 256 + kp] = pack_h2(v0, v1);
}

// ---------- x -> fp16 pack ----------
__global__ void xh_kernel(const float* __restrict__ x, int total) {
    int i = blockIdx.x * blockDim.x + threadIdx.x;
    if (i >= total) return;
    float2 v = *reinterpret_cast<const float2*>(x + 2 * (size_t)i);
    g_xh[i] = pack_h2(v.x, v.y);
}

// ---------- degree count ----------
__global__ void deg_kernel(const int* __restrict__ ei, int E) {
    int i = blockIdx.x * blockDim.x + threadIdx.x;
    if (i < E) atomicAdd(&g_deg[ei[E + i]], 1);
}

__global__ void dinv_kernel(int n) {
    int i = blockIdx.x * blockDim.x + threadIdx.x;
    if (i < n) g_dinv[i] = rsqrtf((float)(g_deg[i] + 1));  // +1 self loop
}

// ---------- FP16 tensor-core GEMM (ldmatrix + cp.async double buffer) ----------
__device__ __forceinline__ void mma_f16(float* d, const uint32_t* a, const uint32_t* b) {
    asm volatile("mma.sync.aligned.m16n8k16.row.col.f32.f16.f16.f32 "
                 "{%0,%1,%2,%3},{%4,%5,%6,%7},{%8,%9},{%0,%1,%2,%3};"
                 : "+f"(d[0]), "+f"(d[1]), "+f"(d[2]), "+f"(d[3])
                 : "r"(a[0]), "r"(a[1]), "r"(a[2]), "r"(a[3]),
                   "r"(b[0]), "r"(b[1]));
}

__device__ __forceinline__ void ldsm_x4(uint32_t& r0, uint32_t& r1,
                                        uint32_t& r2, uint32_t& r3, uint32_t addr) {
    asm volatile("ldmatrix.sync.aligned.m8n8.x4.shared.b16 {%0,%1,%2,%3}, [%4];"
                 : "=r"(r0), "=r"(r1), "=r"(r2), "=r"(r3) : "r"(addr));
}

__device__ __forceinline__ uint32_t smem_u32(const void* p) {
    uint32_t a;
    asm("{ .reg .u64 t; cvta.to.shared.u64 t, %1; cvt.u32.u64 %0, t; }" : "=r"(a) : "l"(p));
    return a;
}

__device__ __forceinline__ void cp16(uint32_t dst, const void* src, int srcBytes) {
    asm volatile("cp.async.cg.shared.global [%0], [%1], 16, %2;"
                 :: "r"(dst), "l"(src), "r"(srcBytes) : "memory");
}

#define GBM 128
#define GBN 128
#define GBK 32
#define HP  20    // row pitch in words (16 used + 4 pad) -> conflict-free LDSM

__global__ __launch_bounds__(256, 2)
void f16gemm_kernel(int M) {
    __shared__ uint32_t As[2][GBM][HP];
    __shared__ uint32_t Bs[2][GBN][HP];
    const int t    = threadIdx.x;
    const int wid  = t >> 5;
    const int lane = t & 31;
    const int wm   = wid & 3;
    const int wn   = wid >> 2;
    const int lr   = lane >> 2;
    const int lc   = lane & 3;
    const int m0   = blockIdx.y * GBM;
    const int n0   = blockIdx.x * GBN;

    const int lrow = (lane & 7) + ((lane >> 3) & 1) * 8;
    const int lcol = (lane >> 4) * 4;
    const uint32_t sbA = smem_u32(&As[0][0][0]);
    const uint32_t sbB = smem_u32(&Bs[0][0][0]);
    uint32_t aAddr[2], bAddr[4];
#pragma unroll
    for (int mt = 0; mt < 2; mt++)
        aAddr[mt] = sbA + (uint32_t)(((wm * 32 + mt * 16 + lrow) * HP + lcol) * 4);
#pragma unroll
    for (int ng = 0; ng < 4; ng++)
        bAddr[ng] = sbB + (uint32_t)(((wn * 64 + ng * 16 + lrow) * HP + lcol) * 4);
    const uint32_t bufA = (uint32_t)(GBM * HP * 4);
    const uint32_t bufB = (uint32_t)(GBN * HP * 4);

    float acc[2][8][4];
#pragma unroll
    for (int mt = 0; mt < 2; mt++)
#pragma unroll
        for (int nt = 0; nt < 8; nt++)
#pragma unroll
            for (int r = 0; r < 4; r++) acc[mt][nt][r] = 0.f;

    auto issue = [&](int kt, int b) {
        const int kw = kt >> 1;
#pragma unroll
        for (int i = 0; i < 2; i++) {
            int f   = t + i * 256;
            int row = f >> 2;
            int c16 = (f & 3) * 4;
            uint32_t dA = smem_u32(&As[b][row][c16]);
            const uint32_t* sA = g_xh + (size_t)(m0 + row) * 256 + kw + c16;
            cp16(dA, sA, (m0 + row < M) ? 16 : 0);
            uint32_t dB = smem_u32(&Bs[b][row][c16]);
            const uint32_t* sB = g_wh + (size_t)(n0 + row) * 256 + kw + c16;
            cp16(dB, sB, (n0 + row < NCAT) ? 16 : 0);
        }
        asm volatile("cp.async.commit_group;" ::: "memory");
    };

    issue(0, 0);
    int buf = 0;

    for (int kt = 0; kt < INF; kt += GBK) {
        const bool more = (kt + GBK < INF);
        if (more) issue(kt + GBK, buf ^ 1);
        if (more) asm volatile("cp.async.wait_group 1;" ::: "memory");
        else      asm volatile("cp.async.wait_group 0;" ::: "memory");
        __syncthreads();

        const uint32_t offA = buf ? bufA : 0u;
        const uint32_t offB = buf ? bufB : 0u;
#pragma unroll
        for (int s = 0; s < 2; s++) {
            const uint32_t so = (uint32_t)(s * 8 * 4);
            uint32_t af[2][4];
#pragma unroll
            for (int mt = 0; mt < 2; mt++)
                ldsm_x4(af[mt][0], af[mt][1], af[mt][2], af[mt][3],
                        aAddr[mt] + offA + so);
            uint32_t bf[8][2];
#pragma unroll
            for (int ng = 0; ng < 4; ng++) {
                uint32_t q0, q1, q2, q3;
                ldsm_x4(q0, q1, q2, q3, bAddr[ng] + offB + so);
                bf[2 * ng][0]     = q0;
                bf[2 * ng + 1][0] = q1;
                bf[2 * ng][1]     = q2;
                bf[2 * ng + 1][1] = q3;
            }
#pragma unroll
            for (int nt = 0; nt < 8; nt++)
#pragma unroll
                for (int mt = 0; mt < 2; mt++)
                    mma_f16(acc[mt][nt], af[mt], bf[nt]);
        }
        __syncthreads();
        buf ^= 1;
    }

    // store: all outputs fp16. bases blocks -> g_bases_h; rest -> g_rest_h
    const bool isBases = (n0 < AGGC);   // block-uniform
#pragma unroll
    for (int mt = 0; mt < 2; mt++) {
#pragma unroll
        for (int nt = 0; nt < 8; nt++) {
            int row = m0 + wm * 32 + mt * 16 + lr;
            int col = n0 + wn * 64 + nt * 8 + 2 * lc;
            if (isBases) {
                if (row < M)
                    g_bases_h[(size_t)row * 128 + (col >> 1)] =
                        pack_h2(acc[mt][nt][0], acc[mt][nt][1]);
                if (row + 8 < M)
                    g_bases_h[(size_t)(row + 8) * 128 + (col >> 1)] =
                        pack_h2(acc[mt][nt][2], acc[mt][nt][3]);
            } else if (col < NCAT) {
                int rw = (col - AGGC) >> 1;
                if (row < M)
                    g_rest_h[(size_t)row * RESTW + rw] =
                        pack_h2(acc[mt][nt][0], acc[mt][nt][1]);
                if (row + 8 < M)
                    g_rest_h[(size_t)(row + 8) * RESTW + rw] =
                        pack_h2(acc[mt][nt][2], acc[mt][nt][3]);
            }
        }
    }
}

// ---------- edge scatter: agg[dst] += bases_h[src] * nrm ----------
__device__ __forceinline__ void red_add_v4(float* addr, float a, float b, float c, float d) {
    asm volatile("red.global.add.v4.f32 [%0], {%1, %2, %3, %4};"
                 :: "l"(addr), "f"(a), "f"(b), "f"(c), "f"(d) : "memory");
}

__global__ void scatter_kernel(const int* __restrict__ ei, int E) {
    int w = (blockIdx.x * blockDim.x + threadIdx.x) >> 5;
    if (w >= E) return;
    int lane = threadIdx.x & 31;
    int src = __ldg(ei + w);
    int dst = __ldg(ei + E + w);
    float nrm = __ldg(g_dinv + src) * __ldg(g_dinv + dst);
    const uint2* brow = reinterpret_cast<const uint2*>(g_bases_h + (size_t)src * 128);
    float* arow = g_agg + (size_t)dst * AGGC;
#pragma unroll
    for (int i = 0; i < 2; i++) {
        int q = lane + i * 32;
        uint2 h = __ldg(brow + q);
        float2 f0 = __half22float2(*reinterpret_cast<__half2*>(&h.x));
        float2 f1 = __half22float2(*reinterpret_cast<__half2*>(&h.y));
        red_add_v4(arow + q * 4, f0.x * nrm, f0.y * nrm, f1.x * nrm, f1.y * nrm);
    }
}

// ---------- combine: einsum + biases + residual + LayerNorm + ReLU ----------
// thread t owns output column pairs (2t,2t+1) and (256+2t,256+2t+1)
__global__ __launch_bounds__(128)
void combine_kernel(const float* __restrict__ b_comb,
                    const float* __restrict__ conv_bias,
                    const float* __restrict__ b_res,
                    const float* __restrict__ gamma,
                    const float* __restrict__ beta,
                    float* __restrict__ out) {
    int v = blockIdx.x;
    int tid = threadIdx.x;
    __shared__ float sagg[AGGC];
    __shared__ float sw[WCOMB];
    __shared__ float red[8];

    float d = g_dinv[v];
    float d2 = d * d;
    const uint32_t* rh = g_rest_h + (size_t)v * RESTW;
    const float* ag = g_agg + (size_t)v * AGGC;

    // agg row + self-loop term (bases from fp16 copy)
    {
        uint32_t h = g_bases_h[(size_t)v * 128 + tid];
        float2 bf = __half22float2(*reinterpret_cast<__half2*>(&h));
        float2 av = *reinterpret_cast<const float2*>(ag + 2 * tid);
        sagg[2 * tid]     = av.x + bf.x * d2;
        sagg[2 * tid + 1] = av.y + bf.y * d2;
    }
    // weightings: rest words 0..15 hold cols 0..31
    if (tid < 16) {
        uint32_t h = rh[tid];
        float2 w2 = __half22float2(*reinterpret_cast<__half2*>(&h));
        sw[2 * tid]     = w2.x + b_comb[2 * tid];
        sw[2 * tid + 1] = w2.y + b_comb[2 * tid + 1];
    }
    __syncthreads();

    float val[2][2];
    float s = 0.f, sq = 0.f;
#pragma unroll
    for (int j = 0; j < 2; j++) {
        int c0 = 2 * tid + j * 256;          // even
        int h  = c0 >> 6, f = c0 & 63;       // c0,c0+1 same head
        const float* wv = &sw[h * 4];
        uint32_t rw = rh[16 + tid + j * 128];  // residual half2 for (c0,c0+1)
        float2 res = __half22float2(*reinterpret_cast<__half2*>(&rw));
        float2 cb  = *reinterpret_cast<const float2*>(conv_bias + c0);
        float2 br  = *reinterpret_cast<const float2*>(b_res + c0);
        float a0 = wv[0] * sagg[f]     + wv[1] * sagg[64 + f]
                 + wv[2] * sagg[128 + f] + wv[3] * sagg[192 + f]
                 + cb.x + res.x + br.x;
        float a1 = wv[0] * sagg[f + 1]     + wv[1] * sagg[64 + f + 1]
                 + wv[2] * sagg[128 + f + 1] + wv[3] * sagg[192 + f + 1]
                 + cb.y + res.y + br.y;
        val[j][0] = a0; val[j][1] = a1;
        s  += a0 + a1;
        sq += a0 * a0 + a1 * a1;
    }
#pragma unroll
    for (int o = 16; o > 0; o >>= 1) {
        s  += __shfl_xor_sync(0xffffffffu, s, o);
        sq += __shfl_xor_sync(0xffffffffu, sq, o);
    }
    if ((tid & 31) == 0) { red[tid >> 5] = s; red[4 + (tid >> 5)] = sq; }
    __syncthreads();
    s  = red[0] + red[1] + red[2] + red[3];
    sq = red[4] + red[5] + red[6] + red[7];
    float mean = s * (1.f / OUTF);
    float var  = sq * (1.f / OUTF) - mean * mean;
    float rstd = rsqrtf(var + LNEPS);
#pragma unroll
    for (int j = 0; j < 2; j++) {
        int c0 = 2 * tid + j * 256;
        float2 gm = *reinterpret_cast<const float2*>(gamma + c0);
        float2 bt = *reinterpret_cast<const float2*>(beta + c0);
        float o0 = (val[j][0] - mean) * rstd * gm.x + bt.x;
        float o1 = (val[j][1] - mean) * rstd * gm.y + bt.y;
        float2 o = make_float2(fmaxf(o0, 0.f), fmaxf(o1, 0.f));
        *reinterpret_cast<float2*>(out + (size_t)v * OUTF + c0) = o;
    }
}

extern "C" void kernel_launch(void* const* d_in, const int* in_sizes, int n_in,
                              void* d_out, int out_size) {
    const float* x     = (const float*)d_in[0];
    const int*   ei    = (const int*)  d_in[1];
    const float* Wb    = (const float*)d_in[2];
    const float* Wc    = (const float*)d_in[3];
    const float* bcomb = (const float*)d_in[4];
    const float* cbias = (const float*)d_in[5];
    const float* Wr    = (const float*)d_in[6];
    const float* bres  = (const float*)d_in[7];
    const float* gamma = (const float*)d_in[8];
    const float* beta  = (const float*)d_in[9];
    float* out = (float*)d_out;

    const int N = in_sizes[0] / INF;
    const int E = in_sizes[1] / 2;

    // 1. zero agg + deg
    {
        int nAgg4 = (N * AGGC) / 4;
        zero_kernel<<<(nAgg4 + 255) / 256, 256>>>(nAgg4, N);
    }
    // 2. weights -> fp16 [c][kpair]; x -> fp16 [n][kpair]
    concatw_kernel<<<(NCAT * 256 + 255) / 256, 256>>>(Wb, Wc, Wr);
    xh_kernel<<<(N * 256 + 255) / 256, 256>>>(x, N * 256);
    // 3. degrees
    deg_kernel<<<(E + 255) / 256, 256>>>(ei, E);
    dinv_kernel<<<(N + 255) / 256, 256>>>(N);
    // 4. fused GEMM (FP16 tensor cores, cp.async staged, fp16 outputs)
    {
        dim3 grid((NCAT + GBN - 1) / GBN, (N + GBM - 1) / GBM);
        f16gemm_kernel<<<grid, 256>>>(N);
    }
    // 5. edge scatter (fp16 bases reads, v4 reduction atomics)
    {
        long long threads = (long long)E * 32;
        int blocks = (int)((threads + 255) / 256);
        scatter_kernel<<<blocks, 256>>>(ei, E);
    }
    // 6. combine + LayerNorm + ReLU
    combine_kernel<<<N, 128>>>(bcomb, cbias, bres, gamma, beta, out);
}

// round 16
// speedup vs baseline: 1.2639x; 1.0096x over previous
#include <cuda_runtime.h>
#include <cuda_fp16.h>
#include <cstdint>

// Problem constants (fixed shapes for this problem instance)
#define NODES   50000
#define EDGES   800000
#define INF     512
#define OUTF    512
#define HEADS   8
#define NBASES  4
#define FHD     64          // OUTF/HEADS
#define AGGC    256         // NBASES*FHD
#define WCOMB   32          // HEADS*NBASES
#define NCAT    800         // 256 + 32 + 512 concatenated GEMM output cols
#define RESTW   272         // (WCOMB+OUTF)/2 half2 words per node
#define LNEPS   1e-5f

// ---------- device scratch (static allocation; no cudaMalloc allowed) ----------
__device__ uint32_t g_wh[(size_t)NCAT * 256];         // fp16 weights, [c][kpair] (~1.6MB)
__device__ uint32_t g_xh[(size_t)NODES * 256];        // fp16 x, [n][kpair] (~51MB)
__device__ uint32_t g_rest_h[(size_t)NODES * RESTW];  // fp16 comb+res [N,272] (~54MB)
__device__ uint32_t g_bases_h[(size_t)NODES * 128];   // bases as half2 [N,128] (~25.6MB)
__device__ float    g_agg[(size_t)NODES * AGGC];      // symnorm aggregation [N,256] (~51MB)
__device__ float    g_dinv[NODES];
__device__ int      g_deg[NODES];

// ---------- zero agg + deg ----------
__global__ void zero_kernel(int nAgg4, int nDeg) {
    int i = blockIdx.x * blockDim.x + threadIdx.x;
    if (i < nAgg4) reinterpret_cast<float4*>(g_agg)[i] = make_float4(0.f, 0.f, 0.f, 0.f);
    if (i < nDeg)  g_deg[i] = 0;
}

__device__ __forceinline__ uint32_t pack_h2(float lo, float hi) {
    __half2 h = __floats2half2_rn(lo, hi);
    return *reinterpret_cast<uint32_t*>(&h);
}

// ---------- concat + transpose weights directly to fp16 [c][kpair] ----------
__global__ void concatw_kernel(const float* __restrict__ Wb,
                               const float* __restrict__ Wc,
                               const float* __restrict__ Wr) {
    int i = blockIdx.x * blockDim.x + threadIdx.x;
    if (i >= NCAT * 256) return;
    int kp = i & 255;
    int c  = i >> 8;
    int k0 = 2 * kp, k1 = 2 * kp + 1;
    float v0, v1;
    if (c < AGGC) {
        v0 = Wb[k0 * AGGC + c]; v1 = Wb[k1 * AGGC + c];
    } else if (c < AGGC + WCOMB) {
        v0 = Wc[k0 * WCOMB + (c - AGGC)]; v1 = Wc[k1 * WCOMB + (c - AGGC)];
    } else {
        v0 = Wr[k0 * OUTF + (c - AGGC - WCOMB)]; v1 = Wr[k1 * OUTF + (c - AGGC - WCOMB)];
    }
    g_wh[(size_t)c * 256 + kp] = pack_h2(v0, v1);
}

// ---------- x -> fp16 pack ----------
__global__ void xh_kernel(const float* __restrict__ x, int total) {
    int i = blockIdx.x * blockDim.x + threadIdx.x;
    if (i >= total) return;
    float2 v = *reinterpret_cast<const float2*>(x + 2 * (size_t)i);
    g_xh[i] = pack_h2(v.x, v.y);
}

// ---------- degree count ----------
__global__ void deg_kernel(const int* __restrict__ ei, int E) {
    int i = blockIdx.x * blockDim.x + threadIdx.x;
    if (i < E) atomicAdd(&g_deg[ei[E + i]], 1);
}

__global__ void dinv_kernel(int n) {
    int i = blockIdx.x * blockDim.x + threadIdx.x;
    if (i < n) g_dinv[i] = rsqrtf((float)(g_deg[i] + 1));  // +1 self loop
}

// ---------- FP16 tensor-core GEMM (ldmatrix + cp.async double buffer) ----------
__device__ __forceinline__ void mma_f16(float* d, const uint32_t* a, const uint32_t* b) {
    asm volatile("mma.sync.aligned.m16n8k16.row.col.f32.f16.f16.f32 "
                 "{%0,%1,%2,%3},{%4,%5,%6,%7},{%8,%9},{%0,%1,%2,%3};"
                 : "+f"(d[0]), "+f"(d[1]), "+f"(d[2]), "+f"(d[3])
                 : "r"(a[0]), "r"(a[1]), "r"(a[2]), "r"(a[3]),
                   "r"(b[0]), "r"(b[1]));
}

__device__ __forceinline__ void ldsm_x4(uint32_t& r0, uint32_t& r1,
                                        uint32_t& r2, uint32_t& r3, uint32_t addr) {
    asm volatile("ldmatrix.sync.aligned.m8n8.x4.shared.b16 {%0,%1,%2,%3}, [%4];"
                 : "=r"(r0), "=r"(r1), "=r"(r2), "=r"(r3) : "r"(addr));
}

__device__ __forceinline__ uint32_t smem_u32(const void* p) {
    uint32_t a;
    asm("{ .reg .u64 t; cvta.to.shared.u64 t, %1; cvt.u32.u64 %0, t; }" : "=r"(a) : "l"(p));
    return a;
}

__device__ __forceinline__ void cp16(uint32_t dst, const void* src, int srcBytes) {
    asm volatile("cp.async.cg.shared.global [%0], [%1], 16, %2;"
                 :: "r"(dst), "l"(src), "r"(srcBytes) : "memory");
}

#define GBM 128
#define GBN 128
#define GBK 32
#define HP  20    // row pitch in words (16 used + 4 pad) -> conflict-free LDSM

__global__ __launch_bounds__(256, 2)
void f16gemm_kernel(int M) {
    __shared__ uint32_t As[2][GBM][HP];
    __shared__ uint32_t Bs[2][GBN][HP];
    const int t    = threadIdx.x;
    const int wid  = t >> 5;
    const int lane = t & 31;
    const int wm   = wid & 3;
    const int wn   = wid >> 2;
    const int lr   = lane >> 2;
    const int lc   = lane & 3;
    const int m0   = blockIdx.y * GBM;
    const int n0   = blockIdx.x * GBN;

    const int lrow = (lane & 7) + ((lane >> 3) & 1) * 8;
    const int lcol = (lane >> 4) * 4;
    const uint32_t sbA = smem_u32(&As[0][0][0]);
    const uint32_t sbB = smem_u32(&Bs[0][0][0]);
    uint32_t aAddr[2], bAddr[4];
#pragma unroll
    for (int mt = 0; mt < 2; mt++)
        aAddr[mt] = sbA + (uint32_t)(((wm * 32 + mt * 16 + lrow) * HP + lcol) * 4);
#pragma unroll
    for (int ng = 0; ng < 4; ng++)
        bAddr[ng] = sbB + (uint32_t)(((wn * 64 + ng * 16 + lrow) * HP + lcol) * 4);
    const uint32_t bufA = (uint32_t)(GBM * HP * 4);
    const uint32_t bufB = (uint32_t)(GBN * HP * 4);

    float acc[2][8][4];
#pragma unroll
    for (int mt = 0; mt < 2; mt++)
#pragma unroll
        for (int nt = 0; nt < 8; nt++)
#pragma unroll
            for (int r = 0; r < 4; r++) acc[mt][nt][r] = 0.f;

    auto issue = [&](int kt, int b) {
        const int kw = kt >> 1;
#pragma unroll
        for (int i = 0; i < 2; i++) {
            int f   = t + i * 256;
            int row = f >> 2;
            int c16 = (f & 3) * 4;
            uint32_t dA = smem_u32(&As[b][row][c16]);
            const uint32_t* sA = g_xh + (size_t)(m0 + row) * 256 + kw + c16;
            cp16(dA, sA, (m0 + row < M) ? 16 : 0);
            uint32_t dB = smem_u32(&Bs[b][row][c16]);
            const uint32_t* sB = g_wh + (size_t)(n0 + row) * 256 + kw + c16;
            cp16(dB, sB, (n0 + row < NCAT) ? 16 : 0);
        }
        asm volatile("cp.async.commit_group;" ::: "memory");
    };

    issue(0, 0);
    int buf = 0;

    for (int kt = 0; kt < INF; kt += GBK) {
        const bool more = (kt + GBK < INF);
        if (more) issue(kt + GBK, buf ^ 1);
        if (more) asm volatile("cp.async.wait_group 1;" ::: "memory");
        else      asm volatile("cp.async.wait_group 0;" ::: "memory");
        __syncthreads();

        const uint32_t offA = buf ? bufA : 0u;
        const uint32_t offB = buf ? bufB : 0u;
#pragma unroll
        for (int s = 0; s < 2; s++) {
            const uint32_t so = (uint32_t)(s * 8 * 4);
            uint32_t af[2][4];
#pragma unroll
            for (int mt = 0; mt < 2; mt++)
                ldsm_x4(af[mt][0], af[mt][1], af[mt][2], af[mt][3],
                        aAddr[mt] + offA + so);
            uint32_t bf[8][2];
#pragma unroll
            for (int ng = 0; ng < 4; ng++) {
                uint32_t q0, q1, q2, q3;
                ldsm_x4(q0, q1, q2, q3, bAddr[ng] + offB + so);
                bf[2 * ng][0]     = q0;
                bf[2 * ng + 1][0] = q1;
                bf[2 * ng][1]     = q2;
                bf[2 * ng + 1][1] = q3;
            }
#pragma unroll
            for (int nt = 0; nt < 8; nt++)
#pragma unroll
                for (int mt = 0; mt < 2; mt++)
                    mma_f16(acc[mt][nt], af[mt], bf[nt]);
        }
        __syncthreads();
        buf ^= 1;
    }

    // store: all outputs fp16. bases blocks -> g_bases_h; rest -> g_rest_h
    const bool isBases = (n0 < AGGC);   // block-uniform
#pragma unroll
    for (int mt = 0; mt < 2; mt++) {
#pragma unroll
        for (int nt = 0; nt < 8; nt++) {
            int row = m0 + wm * 32 + mt * 16 + lr;
            int col = n0 + wn * 64 + nt * 8 + 2 * lc;
            if (isBases) {
                if (row < M)
                    g_bases_h[(size_t)row * 128 + (col >> 1)] =
                        pack_h2(acc[mt][nt][0], acc[mt][nt][1]);
                if (row + 8 < M)
                    g_bases_h[(size_t)(row + 8) * 128 + (col >> 1)] =
                        pack_h2(acc[mt][nt][2], acc[mt][nt][3]);
            } else if (col < NCAT) {
                int rw = (col - AGGC) >> 1;
                if (row < M)
                    g_rest_h[(size_t)row * RESTW + rw] =
                        pack_h2(acc[mt][nt][0], acc[mt][nt][1]);
                if (row + 8 < M)
                    g_rest_h[(size_t)(row + 8) * RESTW + rw] =
                        pack_h2(acc[mt][nt][2], acc[mt][nt][3]);
            }
        }
    }
}

// ---------- edge scatter: agg[dst] += bases_h[src] * nrm ----------
__device__ __forceinline__ void red_add_v4(float* addr, float a, float b, float c, float d) {
    asm volatile("red.global.add.v4.f32 [%0], {%1, %2, %3, %4};"
                 :: "l"(addr), "f"(a), "f"(b), "f"(c), "f"(d) : "memory");
}

__global__ void scatter_kernel(const int* __restrict__ ei, int E) {
    int w = (blockIdx.x * blockDim.x + threadIdx.x) >> 5;
    if (w >= E) return;
    int lane = threadIdx.x & 31;
    int src = __ldg(ei + w);
    int dst = __ldg(ei + E + w);
    float nrm = __ldg(g_dinv + src) * __ldg(g_dinv + dst);
    const uint2* brow = reinterpret_cast<const uint2*>(g_bases_h + (size_t)src * 128);
    float* arow = g_agg + (size_t)dst * AGGC;
#pragma unroll
    for (int i = 0; i < 2; i++) {
        int q = lane + i * 32;
        uint2 h = __ldg(brow + q);
        float2 f0 = __half22float2(*reinterpret_cast<__half2*>(&h.x));
        float2 f1 = __half22float2(*reinterpret_cast<__half2*>(&h.y));
        red_add_v4(arow + q * 4, f0.x * nrm, f0.y * nrm, f1.x * nrm, f1.y * nrm);
    }
}

// ---------- combine: einsum + biases + residual + LayerNorm + ReLU ----------
// thread t owns output column pairs (2t,2t+1) and (256+2t,256+2t+1)
__global__ __launch_bounds__(128)
void combine_kernel(const float* __restrict__ b_comb,
                    const float* __restrict__ conv_bias,
                    const float* __restrict__ b_res,
                    const float* __restrict__ gamma,
                    const float* __restrict__ beta,
                    float* __restrict__ out) {
    int v = blockIdx.x;
    int tid = threadIdx.x;
    __shared__ float sagg[AGGC];
    __shared__ float sw[WCOMB];
    __shared__ float red[8];

    float d = g_dinv[v];
    float d2 = d * d;
    const uint32_t* rh = g_rest_h + (size_t)v * RESTW;
    const float* ag = g_agg + (size_t)v * AGGC;

    // agg row + self-loop term (bases from fp16 copy)
    {
        uint32_t h = g_bases_h[(size_t)v * 128 + tid];
        float2 bf = __half22float2(*reinterpret_cast<__half2*>(&h));
        float2 av = *reinterpret_cast<const float2*>(ag + 2 * tid);
        sagg[2 * tid]     = av.x + bf.x * d2;
        sagg[2 * tid + 1] = av.y + bf.y * d2;
    }
    // weightings: rest words 0..15 hold cols 0..31
    if (tid < 16) {
        uint32_t h = rh[tid];
        float2 w2 = __half22float2(*reinterpret_cast<__half2*>(&h));
        sw[2 * tid]     = w2.x + b_comb[2 * tid];
        sw[2 * tid + 1] = w2.y + b_comb[2 * tid + 1];
    }
    __syncthreads();

    float val[2][2];
    float s = 0.f, sq = 0.f;
#pragma unroll
    for (int j = 0; j < 2; j++) {
        int c0 = 2 * tid + j * 256;
        int h  = c0 >> 6, f = c0 & 63;
        const float* wv = &sw[h * 4];
        uint32_t rw = rh[16 + tid + j * 128];
        float2 res = __half22float2(*reinterpret_cast<__half2*>(&rw));
        float2 cb  = *reinterpret_cast<const float2*>(conv_bias + c0);
        float2 br  = *reinterpret_cast<const float2*>(b_res + c0);
        float a0 = wv[0] * sagg[f]     + wv[1] * sagg[64 + f]
                 + wv[2] * sagg[128 + f] + wv[3] * sagg[192 + f]
                 + cb.x + res.x + br.x;
        float a1 = wv[0] * sagg[f + 1]     + wv[1] * sagg[64 + f + 1]
                 + wv[2] * sagg[128 + f + 1] + wv[3] * sagg[192 + f + 1]
                 + cb.y + res.y + br.y;
        val[j][0] = a0; val[j][1] = a1;
        s  += a0 + a1;
        sq += a0 * a0 + a1 * a1;
    }
#pragma unroll
    for (int o = 16; o > 0; o >>= 1) {
        s  += __shfl_xor_sync(0xffffffffu, s, o);
        sq += __shfl_xor_sync(0xffffffffu, sq, o);
    }
    if ((tid & 31) == 0) { red[tid >> 5] = s; red[4 + (tid >> 5)] = sq; }
    __syncthreads();
    s  = red[0] + red[1] + red[2] + red[3];
    sq = red[4] + red[5] + red[6] + red[7];
    float mean = s * (1.f / OUTF);
    float var  = sq * (1.f / OUTF) - mean * mean;
    float rstd = rsqrtf(var + LNEPS);
#pragma unroll
    for (int j = 0; j < 2; j++) {
        int c0 = 2 * tid + j * 256;
        float2 gm = *reinterpret_cast<const float2*>(gamma + c0);
        float2 bt = *reinterpret_cast<const float2*>(beta + c0);
        float o0 = (val[j][0] - mean) * rstd * gm.x + bt.x;
        float o1 = (val[j][1] - mean) * rstd * gm.y + bt.y;
        float2 o = make_float2(fmaxf(o0, 0.f), fmaxf(o1, 0.f));
        *reinterpret_cast<float2*>(out + (size_t)v * OUTF + c0) = o;
    }
}

extern "C" void kernel_launch(void* const* d_in, const int* in_sizes, int n_in,
                              void* d_out, int out_size) {
    const float* x     = (const float*)d_in[0];
    const int*   ei    = (const int*)  d_in[1];
    const float* Wb    = (const float*)d_in[2];
    const float* Wc    = (const float*)d_in[3];
    const float* bcomb = (const float*)d_in[4];
    const float* cbias = (const float*)d_in[5];
    const float* Wr    = (const float*)d_in[6];
    const float* bres  = (const float*)d_in[7];
    const float* gamma = (const float*)d_in[8];
    const float* beta  = (const float*)d_in[9];
    float* out = (float*)d_out;

    const int N = in_sizes[0] / INF;
    const int E = in_sizes[1] / 2;

    // Launch order rearranged so the profiler's capture window (launch idx 3)
    // lands on the GEMM. Dependencies preserved: gemm needs concatw+xh;
    // scatter needs gemm+zero+dinv; deg/dinv moved after gemm.
    concatw_kernel<<<(NCAT * 256 + 255) / 256, 256>>>(Wb, Wc, Wr);        // 0
    xh_kernel<<<(N * 256 + 255) / 256, 256>>>(x, N * 256);                // 1
    {
        int nAgg4 = (N * AGGC) / 4;
        zero_kernel<<<(nAgg4 + 255) / 256, 256>>>(nAgg4, N);              // 2
    }
    {
        dim3 grid((NCAT + GBN - 1) / GBN, (N + GBM - 1) / GBM);
        f16gemm_kernel<<<grid, 256>>>(N);                                  // 3 <- profiled
    }
    deg_kernel<<<(E + 255) / 256, 256>>>(ei, E);                           // 4
    dinv_kernel<<<(N + 255) / 256, 256>>>(N);                              // 5
    {
        long long threads = (long long)E * 32;
        int blocks = (int)((threads + 255) / 256);
        scatter_kernel<<<blocks, 256>>>(ei, E);                            // 6
    }
    combine_kernel<<<N, 128>>>(bcomb, cbias, bres, gamma, beta, out);      // 7
}